// round 3
// baseline (speedup 1.0000x reference)
#include <cuda_runtime.h>
#include <cuda_bf16.h>
#include <math.h>
#include <stdint.h>

// ---------------- problem constants ----------------
#define NTOK  8192     // B*S
#define HID   2048
#define INTER 8192
#define RET   128
#define NKEY  64
#define TOPK  8

// ---------------- scratch (__device__ globals; no allocation allowed) ----------------
__device__ __align__(256) __nv_bfloat16 g_x_hi[NTOK * HID];
__device__ __align__(256) __nv_bfloat16 g_x_lo[NTOK * HID];
__device__ __align__(256) __nv_bfloat16 g_wq_hi[HID * RET];
__device__ __align__(256) __nv_bfloat16 g_wq_lo[HID * RET];
__device__ __align__(256) __nv_bfloat16 g_gw_hi[HID * INTER];
__device__ __align__(256) __nv_bfloat16 g_gw_lo[HID * INTER];
__device__ __align__(256) __nv_bfloat16 g_uw_hi[HID * INTER];
__device__ __align__(256) __nv_bfloat16 g_uw_lo[HID * INTER];
__device__ __align__(256) __nv_bfloat16 g_dw_hi[INTER * HID];
__device__ __align__(256) __nv_bfloat16 g_dw_lo[INTER * HID];
__device__ __align__(256) float         g_G[(size_t)NTOK * INTER];      // gate pre-act
__device__ __align__(256) __nv_bfloat16 g_h_hi[(size_t)NTOK * INTER];   // silu(g)*u hi
__device__ __align__(256) __nv_bfloat16 g_h_lo[(size_t)NTOK * INTER];   // silu(g)*u lo
__device__ __align__(256) float         g_Q[NTOK * RET];
__device__ __align__(256) int           g_eidx[NTOK * TOPK];
__device__ __align__(256) float         g_prob[NTOK * TOPK];

// ---------------- helpers ----------------
__device__ __forceinline__ void cp16(uint32_t s, const void* g) {
    asm volatile("cp.async.cg.shared.global [%0], [%1], 16;\n" :: "r"(s), "l"(g));
}
__device__ __forceinline__ void ldsm_x4(uint32_t (&r)[4], uint32_t addr) {
    asm volatile("ldmatrix.sync.aligned.m8n8.x4.shared.b16 {%0,%1,%2,%3}, [%4];"
                 : "=r"(r[0]), "=r"(r[1]), "=r"(r[2]), "=r"(r[3]) : "r"(addr));
}
__device__ __forceinline__ void ldsm_x4t(uint32_t (&r)[4], uint32_t addr) {
    asm volatile("ldmatrix.sync.aligned.m8n8.x4.trans.shared.b16 {%0,%1,%2,%3}, [%4];"
                 : "=r"(r[0]), "=r"(r[1]), "=r"(r[2]), "=r"(r[3]) : "r"(addr));
}
__device__ __forceinline__ void mma16816(float (&c)[4], const uint32_t (&a)[4], const uint32_t (&b)[2]) {
    asm volatile("mma.sync.aligned.m16n8k16.row.col.f32.bf16.bf16.f32 "
                 "{%0,%1,%2,%3},{%4,%5,%6,%7},{%8,%9},{%0,%1,%2,%3};"
                 : "+f"(c[0]), "+f"(c[1]), "+f"(c[2]), "+f"(c[3])
                 : "r"(a[0]), "r"(a[1]), "r"(a[2]), "r"(a[3]), "r"(b[0]), "r"(b[1]));
}

// ---------------- fp32 -> bf16 hi/lo split ----------------
__global__ void split_kernel(const float* __restrict__ in,
                             __nv_bfloat16* __restrict__ hi,
                             __nv_bfloat16* __restrict__ lo, int n) {
    int i = blockIdx.x * blockDim.x + threadIdx.x;
    int stride = gridDim.x * blockDim.x;
    for (; i < n; i += stride) {
        float v = in[i];
        __nv_bfloat16 h = __float2bfloat16(v);
        hi[i] = h;
        lo[i] = __float2bfloat16(v - __bfloat162float(h));
    }
}

// ---------------- bf16x3 GEMM: C = A*B with A=(Ah+Al), B=(Bh+Bl), drop Al*Bl ----------------
// A row-major [M,K] (lda=K), B row-major [K,N] (ldb=N). Tile 128x128x32, 256 threads,
// warp grid 2(m)x4(n), warp tile 64x32, double-buffered cp.async.
// mode 0: Cout[row*N+col] = acc
// mode 1: h = silu(Gin)*acc; split h -> (Hh, Hl) bf16
__global__ void __launch_bounds__(256, 1)
gemm3x_kernel(const __nv_bfloat16* __restrict__ Ah, const __nv_bfloat16* __restrict__ Al,
              const __nv_bfloat16* __restrict__ Bh, const __nv_bfloat16* __restrict__ Bl,
              int M, int N, int K, int lda, int ldb,
              float* __restrict__ Cout, const float* __restrict__ Gin,
              __nv_bfloat16* __restrict__ Hh, __nv_bfloat16* __restrict__ Hl,
              int mode)
{
    extern __shared__ __align__(16) unsigned char smem_raw[];
    const uint32_t sbase = (uint32_t)__cvta_generic_to_shared(smem_raw);
    // A tiles: 128 rows x (32+8) bf16 -> 80B/row, 10240B/stage, 2 stages per matrix
    // B tiles: 32 rows x (128+8) bf16 -> 272B/row, 8704B/stage
    const uint32_t sAh = sbase;
    const uint32_t sAl = sbase + 20480u;
    const uint32_t sBh = sbase + 40960u;
    const uint32_t sBl = sbase + 58368u;

    const int tid  = threadIdx.x;
    const int lane = tid & 31;
    const int warp = tid >> 5;
    const int wm   = warp >> 2;   // 0..1
    const int wn   = warp & 3;    // 0..3
    const int mBlk = blockIdx.y * 128;
    const int nBlk = blockIdx.x * 128;

    float c[4][4][4];
#pragma unroll
    for (int i = 0; i < 4; i++)
#pragma unroll
        for (int j = 0; j < 4; j++)
#pragma unroll
            for (int k = 0; k < 4; k++) c[i][j][k] = 0.f;

    const int KT = K >> 5;

    auto load_stage = [&](int st, int kt) {
        const int k0 = kt << 5;
#pragma unroll
        for (int rep = 0; rep < 2; ++rep) {
            int id  = tid + rep * 256;
            int row = id >> 2, seg = id & 3;               // A: 512 chunks of 16B
            size_t   go = (size_t)(mBlk + row) * lda + k0 + seg * 8;
            uint32_t so = (uint32_t)st * 10240u + (uint32_t)row * 80u + (uint32_t)seg * 16u;
            cp16(sAh + so, Ah + go);
            cp16(sAl + so, Al + go);
        }
#pragma unroll
        for (int rep = 0; rep < 2; ++rep) {
            int id  = tid + rep * 256;
            int row = id >> 4, seg = id & 15;              // B: 512 chunks of 16B
            size_t   go = (size_t)(k0 + row) * ldb + nBlk + seg * 8;
            uint32_t so = (uint32_t)st * 8704u + (uint32_t)row * 272u + (uint32_t)seg * 16u;
            cp16(sBh + so, Bh + go);
            cp16(sBl + so, Bl + go);
        }
    };

    load_stage(0, 0);
    asm volatile("cp.async.commit_group;\n" ::: "memory");

    for (int kt = 0; kt < KT; ++kt) {
        asm volatile("cp.async.wait_group 0;\n" ::: "memory");
        __syncthreads();
        if (kt + 1 < KT) {
            load_stage((kt + 1) & 1, kt + 1);
            asm volatile("cp.async.commit_group;\n" ::: "memory");
        }
        const int st = kt & 1;
#pragma unroll
        for (int kk = 0; kk < 2; ++kk) {   // two k16 steps per 32-slice
            uint32_t ah[4][4], al[4][4], bh[4][2], bl[4][2];
#pragma unroll
            for (int mi = 0; mi < 4; mi++) {
                uint32_t off = (uint32_t)st * 10240u
                             + (uint32_t)(wm * 64 + mi * 16 + (lane & 15)) * 80u
                             + (uint32_t)(kk * 16 + (lane >> 4) * 8) * 2u;
                ldsm_x4(ah[mi], sAh + off);
                ldsm_x4(al[mi], sAl + off);
            }
#pragma unroll
            for (int nj = 0; nj < 2; nj++) {
                uint32_t off = (uint32_t)st * 8704u
                             + (uint32_t)(kk * 16 + (lane & 15)) * 272u
                             + (uint32_t)(wn * 32 + nj * 16 + (lane >> 4) * 8) * 2u;
                uint32_t r[4];
                ldsm_x4t(r, sBh + off);
                bh[2*nj][0] = r[0]; bh[2*nj][1] = r[1];
                bh[2*nj+1][0] = r[2]; bh[2*nj+1][1] = r[3];
                ldsm_x4t(r, sBl + off);
                bl[2*nj][0] = r[0]; bl[2*nj][1] = r[1];
                bl[2*nj+1][0] = r[2]; bl[2*nj+1][1] = r[3];
            }
#pragma unroll
            for (int mi = 0; mi < 4; mi++)
#pragma unroll
                for (int nt = 0; nt < 4; nt++) {
                    mma16816(c[mi][nt], ah[mi], bh[nt]);   // hi*hi
                    mma16816(c[mi][nt], ah[mi], bl[nt]);   // hi*lo
                    mma16816(c[mi][nt], al[mi], bh[nt]);   // lo*hi
                }
        }
        __syncthreads();
    }

    // epilogue
#pragma unroll
    for (int mi = 0; mi < 4; mi++) {
#pragma unroll
        for (int nt = 0; nt < 4; nt++) {
            int row = mBlk + wm * 64 + mi * 16 + (lane >> 2);
            int col = nBlk + wn * 32 + nt * 8 + (lane & 3) * 2;
#pragma unroll
            for (int hrow = 0; hrow < 2; ++hrow) {
                int r = row + hrow * 8;
                size_t i0 = (size_t)r * N + col;
                float v0 = c[mi][nt][hrow * 2 + 0];
                float v1 = c[mi][nt][hrow * 2 + 1];
                if (mode == 0) {
                    Cout[i0]     = v0;
                    Cout[i0 + 1] = v1;
                } else {
                    float gg0 = Gin[i0], gg1 = Gin[i0 + 1];
                    float hv0 = gg0 / (1.f + expf(-gg0)) * v0;
                    float hv1 = gg1 / (1.f + expf(-gg1)) * v1;
                    __nv_bfloat16 h0 = __float2bfloat16(hv0);
                    __nv_bfloat16 h1 = __float2bfloat16(hv1);
                    Hh[i0]     = h0; Hl[i0]     = __float2bfloat16(hv0 - __bfloat162float(h0));
                    Hh[i0 + 1] = h1; Hl[i0 + 1] = __float2bfloat16(hv1 - __bfloat162float(h1));
                }
            }
        }
    }
}

// ---------------- product-key routing: top8 x top8 -> top8, softmax ----------------
// One warp per routed row m (0..8191). Faithful to the reference's (2,N,64) reshape:
// t=0: token m>>1,      retrieval offset (m&1)*64
// t=1: token 4096+m>>1, retrieval offset (m&1)*64
__global__ void __launch_bounds__(256)
routing_kernel(const float* __restrict__ Q, const float* __restrict__ keys,
               int* __restrict__ eidx, float* __restrict__ probs)
{
    const int warp = threadIdx.x >> 5, lane = threadIdx.x & 31;
    const int m = blockIdx.x * 8 + warp;

    __shared__ float s_q[8][128];
    __shared__ float s_tsx[8][8], s_tsy[8][8];
    __shared__ int   s_tix[8][8], s_tiy[8][8];
    __shared__ float s_sel[8][8];
    __shared__ int   s_pos[8][8];

    const int j0 = (m >> 1);
    const int j1 = 4096 + (m >> 1);
    const int o  = (m & 1) * 64;
    s_q[warp][lane]          = Q[j0 * RET + o + lane];
    s_q[warp][lane + 32]     = Q[j0 * RET + o + lane + 32];
    s_q[warp][64 + lane]     = Q[j1 * RET + o + lane];
    s_q[warp][64 + lane + 32]= Q[j1 * RET + o + lane + 32];
    __syncwarp();

    float rx0 = 0.f, rx1 = 0.f, ry0 = 0.f, ry1 = 0.f;
#pragma unroll 8
    for (int d = 0; d < 64; ++d) {
        float qx = s_q[warp][d], qy = s_q[warp][64 + d];
        rx0 += qx * keys[d * 64 + lane];
        rx1 += qx * keys[d * 64 + lane + 32];
        ry0 += qy * keys[4096 + d * 64 + lane];
        ry1 += qy * keys[4096 + d * 64 + lane + 32];
    }

    // top-8 of rx (64 candidates), ties -> lower index
#pragma unroll 1
    for (int r = 0; r < 8; ++r) {
        float v; int i;
        if (rx0 >= rx1) { v = rx0; i = lane; } else { v = rx1; i = lane + 32; }
#pragma unroll
        for (int s = 16; s; s >>= 1) {
            float ov = __shfl_xor_sync(0xffffffffu, v, s);
            int   oi = __shfl_xor_sync(0xffffffffu, i, s);
            if (ov > v || (ov == v && oi < i)) { v = ov; i = oi; }
        }
        if (lane == 0) { s_tsx[warp][r] = v; s_tix[warp][r] = i; }
        if (i == lane)      rx0 = -INFINITY;
        if (i == lane + 32) rx1 = -INFINITY;
    }
#pragma unroll 1
    for (int r = 0; r < 8; ++r) {
        float v; int i;
        if (ry0 >= ry1) { v = ry0; i = lane; } else { v = ry1; i = lane + 32; }
#pragma unroll
        for (int s = 16; s; s >>= 1) {
            float ov = __shfl_xor_sync(0xffffffffu, v, s);
            int   oi = __shfl_xor_sync(0xffffffffu, i, s);
            if (ov > v || (ov == v && oi < i)) { v = ov; i = oi; }
        }
        if (lane == 0) { s_tsy[warp][r] = v; s_tiy[warp][r] = i; }
        if (i == lane)      ry0 = -INFINITY;
        if (i == lane + 32) ry1 = -INFINITY;
    }
    __syncwarp();

    // 64 combos: position p = i*8 + j (matches reference flattening/tie order)
    float c0 = s_tsx[warp][lane >> 3]        + s_tsy[warp][lane & 7];
    float c1 = s_tsx[warp][(lane + 32) >> 3] + s_tsy[warp][(lane + 32) & 7];
#pragma unroll 1
    for (int r = 0; r < 8; ++r) {
        float v; int p;
        if (c0 >= c1) { v = c0; p = lane; } else { v = c1; p = lane + 32; }
#pragma unroll
        for (int s = 16; s; s >>= 1) {
            float ov = __shfl_xor_sync(0xffffffffu, v, s);
            int   op = __shfl_xor_sync(0xffffffffu, p, s);
            if (ov > v || (ov == v && op < p)) { v = ov; p = op; }
        }
        if (lane == 0) { s_sel[warp][r] = v; s_pos[warp][r] = p; }
        if (p == lane)      c0 = -INFINITY;
        if (p == lane + 32) c1 = -INFINITY;
    }
    __syncwarp();

    if (lane < 8) {
        float mx = s_sel[warp][0];                 // extraction is descending
        float e  = expf(s_sel[warp][lane] - mx);
        float sum = e;
#pragma unroll
        for (int s = 4; s; s >>= 1) sum += __shfl_xor_sync(0xffu, sum, s);
        int p  = s_pos[warp][lane];
        int ex = s_tix[warp][p >> 3] * 64 + s_tiy[warp][p & 7];
        eidx[m * TOPK + lane]  = ex;
        probs[m * TOPK + lane] = e / sum;
    }
}

// ---------------- per-token expert compute (adds into d_out) ----------------
__global__ void __launch_bounds__(256)
expert_kernel(const float* __restrict__ x, const float* __restrict__ down_embed,
              const float* __restrict__ up_embed, const int* __restrict__ eidx,
              const float* __restrict__ probs, float* __restrict__ out)
{
    const int n = blockIdx.x;
    __shared__ __align__(16) float sx[HID];
    __shared__ float coeff[TOPK];
    __shared__ int   se[TOPK];

    const int tid = threadIdx.x;
    const float4* xin = (const float4*)(x + (size_t)n * HID);
    float4* sx4 = (float4*)sx;
    sx4[tid]        = xin[tid];
    sx4[tid + 256]  = xin[tid + 256];
    if (tid < TOPK) se[tid] = eidx[n * TOPK + tid];
    __syncthreads();

    const int w = tid >> 5, lane = tid & 31;
    {
        const float* de = down_embed + (size_t)se[w] * HID;
        float acc = 0.f;
#pragma unroll
        for (int i = 0; i < 64; ++i) acc += sx[i * 32 + lane] * de[i * 32 + lane];
#pragma unroll
        for (int s = 16; s; s >>= 1) acc += __shfl_xor_sync(0xffffffffu, acc, s);
        if (lane == 0)
            coeff[w] = acc / (1.f + expf(-acc)) * probs[n * TOPK + w];
    }
    __syncthreads();

    float cc[TOPK]; int ee[TOPK];
#pragma unroll
    for (int k = 0; k < TOPK; ++k) { cc[k] = coeff[k]; ee[k] = se[k]; }

#pragma unroll
    for (int h = tid; h < HID; h += 256) {
        float acc = out[(size_t)n * HID + h];
#pragma unroll
        for (int k = 0; k < TOPK; ++k)
            acc += cc[k] * up_embed[(size_t)ee[k] * HID + h];
        out[(size_t)n * HID + h] = acc;
    }
}

// ---------------- launch ----------------
extern "C" void kernel_launch(void* const* d_in, const int* in_sizes, int n_in,
                              void* d_out, int out_size) {
    (void)in_sizes; (void)n_in; (void)out_size;
    const float* x    = (const float*)d_in[0];
    const float* Wq   = (const float*)d_in[1];
    const float* keys = (const float*)d_in[2];
    const float* de   = (const float*)d_in[3];
    const float* ue   = (const float*)d_in[4];
    const float* gw   = (const float*)d_in[5];
    const float* uw   = (const float*)d_in[6];
    const float* dw   = (const float*)d_in[7];
    float* out = (float*)d_out;

    void *xh, *xl, *wqh, *wql, *gwh, *gwl, *uwh, *uwl, *dwh, *dwl;
    void *Gp, *hh, *hl, *Qp, *idxp, *pp;
    cudaGetSymbolAddress(&xh,  g_x_hi);  cudaGetSymbolAddress(&xl,  g_x_lo);
    cudaGetSymbolAddress(&wqh, g_wq_hi); cudaGetSymbolAddress(&wql, g_wq_lo);
    cudaGetSymbolAddress(&gwh, g_gw_hi); cudaGetSymbolAddress(&gwl, g_gw_lo);
    cudaGetSymbolAddress(&uwh, g_uw_hi); cudaGetSymbolAddress(&uwl, g_uw_lo);
    cudaGetSymbolAddress(&dwh, g_dw_hi); cudaGetSymbolAddress(&dwl, g_dw_lo);
    cudaGetSymbolAddress(&Gp,  g_G);
    cudaGetSymbolAddress(&hh,  g_h_hi);  cudaGetSymbolAddress(&hl,  g_h_lo);
    cudaGetSymbolAddress(&Qp,  g_Q);
    cudaGetSymbolAddress(&idxp, g_eidx); cudaGetSymbolAddress(&pp, g_prob);

    const int SMEM = 75776;
    cudaFuncSetAttribute(gemm3x_kernel, cudaFuncAttributeMaxDynamicSharedMemorySize, SMEM);

    // fp32 -> bf16 hi/lo splits
    split_kernel<<<2048, 256>>>(x,  (__nv_bfloat16*)xh,  (__nv_bfloat16*)xl,  NTOK * HID);
    split_kernel<<<256,  256>>>(Wq, (__nv_bfloat16*)wqh, (__nv_bfloat16*)wql, HID * RET);
    split_kernel<<<2048, 256>>>(gw, (__nv_bfloat16*)gwh, (__nv_bfloat16*)gwl, HID * INTER);
    split_kernel<<<2048, 256>>>(uw, (__nv_bfloat16*)uwh, (__nv_bfloat16*)uwl, HID * INTER);
    split_kernel<<<2048, 256>>>(dw, (__nv_bfloat16*)dwh, (__nv_bfloat16*)dwl, INTER * HID);

    // Q = x @ W_q  (fp32 out, bf16x3)
    gemm3x_kernel<<<dim3(RET / 128, NTOK / 128), 256, SMEM>>>(
        (__nv_bfloat16*)xh, (__nv_bfloat16*)xl, (__nv_bfloat16*)wqh, (__nv_bfloat16*)wql,
        NTOK, RET, HID, HID, RET, (float*)Qp, nullptr, nullptr, nullptr, 0);

    // product-key routing
    routing_kernel<<<NTOK / 8, 256>>>((const float*)Qp, keys, (int*)idxp, (float*)pp);

    // G = x @ gate_w
    gemm3x_kernel<<<dim3(INTER / 128, NTOK / 128), 256, SMEM>>>(
        (__nv_bfloat16*)xh, (__nv_bfloat16*)xl, (__nv_bfloat16*)gwh, (__nv_bfloat16*)gwl,
        NTOK, INTER, HID, HID, INTER, (float*)Gp, nullptr, nullptr, nullptr, 0);

    // U = x @ up_w, fused epilogue: h = silu(G)*U -> (h_hi, h_lo)
    gemm3x_kernel<<<dim3(INTER / 128, NTOK / 128), 256, SMEM>>>(
        (__nv_bfloat16*)xh, (__nv_bfloat16*)xl, (__nv_bfloat16*)uwh, (__nv_bfloat16*)uwl,
        NTOK, INTER, HID, HID, INTER, nullptr, (const float*)Gp,
        (__nv_bfloat16*)hh, (__nv_bfloat16*)hl, 1);

    // out = h @ down_w  (fp32, full overwrite of d_out)
    gemm3x_kernel<<<dim3(HID / 128, NTOK / 128), 256, SMEM>>>(
        (__nv_bfloat16*)hh, (__nv_bfloat16*)hl, (__nv_bfloat16*)dwh, (__nv_bfloat16*)dwl,
        NTOK, HID, INTER, INTER, HID, out, nullptr, nullptr, nullptr, 0);

    // experts: out += sum_k silu(x·de_k)*softmax_k * ue_k
    expert_kernel<<<NTOK, 256>>>(x, de, ue, (const int*)idxp, (const float*)pp, out);
}

// round 6
// speedup vs baseline: 1.0148x; 1.0148x over previous
#include <cuda_runtime.h>
#include <cuda_bf16.h>
#include <math.h>
#include <stdint.h>

using bf16 = __nv_bfloat16;

// ---------------- problem constants ----------------
#define NTOK  8192     // B*S
#define HID   2048
#define INTER 8192
#define RET   128
#define TOPK  8

// ---------------- scratch (__device__ globals; no allocation allowed) ----------------
__device__ __align__(256) bf16 g_x_hi[(size_t)NTOK * HID];
__device__ __align__(256) bf16 g_x_lo[(size_t)NTOK * HID];
__device__ __align__(256) bf16 g_wq_hi[HID * RET];
__device__ __align__(256) bf16 g_wq_lo[HID * RET];
__device__ __align__(256) bf16 g_gw_hi[(size_t)HID * INTER];
__device__ __align__(256) bf16 g_gw_lo[(size_t)HID * INTER];
__device__ __align__(256) bf16 g_uw_hi[(size_t)HID * INTER];
__device__ __align__(256) bf16 g_uw_lo[(size_t)HID * INTER];
__device__ __align__(256) bf16 g_dw_hi[(size_t)INTER * HID];
__device__ __align__(256) bf16 g_dw_lo[(size_t)INTER * HID];
__device__ __align__(256) float g_G[(size_t)NTOK * INTER];      // gate pre-act
__device__ __align__(256) bf16 g_h_hi[(size_t)NTOK * INTER];
__device__ __align__(256) bf16 g_h_lo[(size_t)NTOK * INTER];
__device__ __align__(256) float g_Q[NTOK * RET];
__device__ __align__(256) int   g_eidx[NTOK * TOPK];
__device__ __align__(256) float g_prob[NTOK * TOPK];

// ---------------- helpers ----------------
__device__ __forceinline__ void cp16(uint32_t s, const void* g) {
    asm volatile("cp.async.cg.shared.global [%0], [%1], 16;\n" :: "r"(s), "l"(g));
}
#define CP_COMMIT() asm volatile("cp.async.commit_group;\n" ::: "memory")
#define CP_WAIT1()  asm volatile("cp.async.wait_group 1;\n" ::: "memory")
#define CP_WAIT0()  asm volatile("cp.async.wait_group 0;\n" ::: "memory")

__device__ __forceinline__ void ldsm_x4(uint32_t (&r)[4], uint32_t addr) {
    asm volatile("ldmatrix.sync.aligned.m8n8.x4.shared.b16 {%0,%1,%2,%3}, [%4];"
                 : "=r"(r[0]), "=r"(r[1]), "=r"(r[2]), "=r"(r[3]) : "r"(addr));
}
__device__ __forceinline__ void ldsm_x4t(uint32_t (&r)[4], uint32_t addr) {
    asm volatile("ldmatrix.sync.aligned.m8n8.x4.trans.shared.b16 {%0,%1,%2,%3}, [%4];"
                 : "=r"(r[0]), "=r"(r[1]), "=r"(r[2]), "=r"(r[3]) : "r"(addr));
}
__device__ __forceinline__ void mma16816(float (&c)[4], const uint32_t (&a)[4], const uint32_t (&b)[2]) {
    asm volatile("mma.sync.aligned.m16n8k16.row.col.f32.bf16.bf16.f32 "
                 "{%0,%1,%2,%3},{%4,%5,%6,%7},{%8,%9},{%0,%1,%2,%3};"
                 : "+f"(c[0]), "+f"(c[1]), "+f"(c[2]), "+f"(c[3])
                 : "r"(a[0]), "r"(a[1]), "r"(a[2]), "r"(a[3]), "r"(b[0]), "r"(b[1]));
}

// ---------------- fp32 -> bf16 hi/lo split ----------------
__global__ void split_kernel(const float* __restrict__ in, bf16* __restrict__ hi,
                             bf16* __restrict__ lo, int n) {
    int i = blockIdx.x * blockDim.x + threadIdx.x;
    int stride = gridDim.x * blockDim.x;
    for (; i < n; i += stride) {
        float v = in[i];
        bf16 h = __float2bfloat16(v);
        hi[i] = h;
        lo[i] = __float2bfloat16(v - __bfloat162float(h));
    }
}

// ============================================================================
// bf16x3 GEMM: C = A*B, A=(Ah+Al), B=(Bh+Bl), drop Al*Bl.
// A row-major [M,K], B row-major [K,N]. CTA tile 256x128x32, 256 threads,
// warp grid 4(m)x2(n), warp tile 64x64, 3-stage cp.async pipeline.
// mode 0: Cout = acc ; mode 1: h = silu(Gin)*acc -> (Hh,Hl) bf16 split.
// ============================================================================
// smem layout per stage (58368 B): Ah[20480] Al[20480] Bh[8704] Bl[8704]
#define ASTG   20480u
#define BSTG   8704u
#define STAGEB 58368u

__global__ void __launch_bounds__(256, 1)
gemm3x_kernel(const bf16* __restrict__ Ah, const bf16* __restrict__ Al,
              const bf16* __restrict__ Bh, const bf16* __restrict__ Bl,
              int M, int N, int K,
              float* __restrict__ Cout, const float* __restrict__ Gin,
              bf16* __restrict__ Hh, bf16* __restrict__ Hl, int mode)
{
    extern __shared__ __align__(16) unsigned char smem_raw[];
    const uint32_t sb = (uint32_t)__cvta_generic_to_shared(smem_raw);

    const int tid  = threadIdx.x;
    const int lane = tid & 31;
    const int warp = tid >> 5;
    const int wm   = warp >> 1;   // 0..3  (m)
    const int wn   = warp & 1;    // 0..1  (n)
    const int mBlk = blockIdx.y * 256;
    const int nBlk = blockIdx.x * 128;
    const int KT   = K >> 5;

    float c[4][8][4];
#pragma unroll
    for (int i = 0; i < 4; i++)
#pragma unroll
        for (int j = 0; j < 8; j++)
#pragma unroll
            for (int k = 0; k < 4; k++) c[i][j][k] = 0.f;

    auto load_stage = [&](int st, int kt) {
        const int k0 = kt << 5;
        const uint32_t base = sb + (uint32_t)st * STAGEB;
#pragma unroll
        for (int r = 0; r < 4; ++r) {                    // A: 1024 ids (256 rows x 4 segs)
            int id = tid + r * 256;
            int row = id >> 2, seg = id & 3;
            size_t go = (size_t)(mBlk + row) * K + k0 + seg * 8;
            uint32_t so = base + (uint32_t)row * 80u + (uint32_t)seg * 16u;
            cp16(so, Ah + go);
            cp16(so + ASTG, Al + go);
        }
#pragma unroll
        for (int r = 0; r < 2; ++r) {                    // B: 512 ids (32 rows x 16 segs)
            int id = tid + r * 256;
            int row = id >> 4, seg = id & 15;
            size_t go = (size_t)(k0 + row) * N + nBlk + seg * 8;
            uint32_t so = base + 2 * ASTG + (uint32_t)row * 272u + (uint32_t)seg * 16u;
            cp16(so, Bh + go);
            cp16(so + BSTG, Bl + go);
        }
    };

    load_stage(0, 0); CP_COMMIT();
    load_stage(1, 1); CP_COMMIT();

    int st = 0;
    for (int kt = 0; kt < KT; ++kt) {
        if (kt + 2 < KT) CP_WAIT1(); else CP_WAIT0();
        __syncthreads();
        if (kt + 2 < KT) {
            int st2 = st + 2; if (st2 >= 3) st2 -= 3;
            load_stage(st2, kt + 2);
            CP_COMMIT();
        }
        const uint32_t base = sb + (uint32_t)st * STAGEB;
#pragma unroll
        for (int kk = 0; kk < 2; ++kk) {
            const uint32_t acol = (uint32_t)(kk * 16 + (lane >> 4) * 8) * 2u;
            const uint32_t brow = base + 2 * ASTG + (uint32_t)(kk * 16 + (lane & 15)) * 272u;

            uint32_t ah[4][4], bh[8][2];
#pragma unroll
            for (int mi = 0; mi < 4; mi++) {
                uint32_t off = base + (uint32_t)(wm * 64 + mi * 16 + (lane & 15)) * 80u + acol;
                ldsm_x4(ah[mi], off);
            }
#pragma unroll
            for (int nj = 0; nj < 4; nj++) {
                uint32_t r[4];
                ldsm_x4t(r, brow + (uint32_t)(wn * 64 + nj * 16 + (lane >> 4) * 8) * 2u);
                bh[2*nj][0] = r[0]; bh[2*nj][1] = r[1];
                bh[2*nj+1][0] = r[2]; bh[2*nj+1][1] = r[3];
            }
#pragma unroll
            for (int mi = 0; mi < 4; mi++)
#pragma unroll
                for (int nt = 0; nt < 8; nt++) mma16816(c[mi][nt], ah[mi], bh[nt]);

            uint32_t al[4][4];
#pragma unroll
            for (int mi = 0; mi < 4; mi++) {
                uint32_t off = base + ASTG + (uint32_t)(wm * 64 + mi * 16 + (lane & 15)) * 80u + acol;
                ldsm_x4(al[mi], off);
            }
#pragma unroll
            for (int mi = 0; mi < 4; mi++)
#pragma unroll
                for (int nt = 0; nt < 8; nt++) mma16816(c[mi][nt], al[mi], bh[nt]);

            uint32_t bl[8][2];
#pragma unroll
            for (int nj = 0; nj < 4; nj++) {
                uint32_t r[4];
                ldsm_x4t(r, brow + BSTG + (uint32_t)(wn * 64 + nj * 16 + (lane >> 4) * 8) * 2u);
                bl[2*nj][0] = r[0]; bl[2*nj][1] = r[1];
                bl[2*nj+1][0] = r[2]; bl[2*nj+1][1] = r[3];
            }
#pragma unroll
            for (int mi = 0; mi < 4; mi++)
#pragma unroll
                for (int nt = 0; nt < 8; nt++) mma16816(c[mi][nt], ah[mi], bl[nt]);
        }
        ++st; if (st >= 3) st = 0;
    }

    // epilogue
#pragma unroll
    for (int mi = 0; mi < 4; mi++) {
#pragma unroll
        for (int nt = 0; nt < 8; nt++) {
            int row = mBlk + wm * 64 + mi * 16 + (lane >> 2);
            int col = nBlk + wn * 64 + nt * 8 + (lane & 3) * 2;
#pragma unroll
            for (int hrow = 0; hrow < 2; ++hrow) {
                int r = row + hrow * 8;
                size_t i0 = (size_t)r * N + col;
                float v0 = c[mi][nt][hrow * 2 + 0];
                float v1 = c[mi][nt][hrow * 2 + 1];
                if (mode == 0) {
                    Cout[i0]     = v0;
                    Cout[i0 + 1] = v1;
                } else {
                    float gg0 = Gin[i0], gg1 = Gin[i0 + 1];
                    float hv0 = gg0 / (1.f + expf(-gg0)) * v0;
                    float hv1 = gg1 / (1.f + expf(-gg1)) * v1;
                    bf16 h0 = __float2bfloat16(hv0);
                    bf16 h1 = __float2bfloat16(hv1);
                    Hh[i0]     = h0; Hl[i0]     = __float2bfloat16(hv0 - __bfloat162float(h0));
                    Hh[i0 + 1] = h1; Hl[i0 + 1] = __float2bfloat16(hv1 - __bfloat162float(h1));
                }
            }
        }
    }
}

// ---------------- product-key routing: top8 x top8 -> top8, softmax ----------------
__global__ void __launch_bounds__(256)
routing_kernel(const float* __restrict__ Q, const float* __restrict__ keys,
               int* __restrict__ eidx, float* __restrict__ probs)
{
    const int warp = threadIdx.x >> 5, lane = threadIdx.x & 31;
    const int m = blockIdx.x * 8 + warp;

    __shared__ float s_q[8][128];
    __shared__ float s_tsx[8][8], s_tsy[8][8];
    __shared__ int   s_tix[8][8], s_tiy[8][8];
    __shared__ float s_sel[8][8];
    __shared__ int   s_pos[8][8];

    const int j0 = (m >> 1);
    const int j1 = 4096 + (m >> 1);
    const int o  = (m & 1) * 64;
    s_q[warp][lane]           = Q[j0 * RET + o + lane];
    s_q[warp][lane + 32]      = Q[j0 * RET + o + lane + 32];
    s_q[warp][64 + lane]      = Q[j1 * RET + o + lane];
    s_q[warp][64 + lane + 32] = Q[j1 * RET + o + lane + 32];
    __syncwarp();

    float rx0 = 0.f, rx1 = 0.f, ry0 = 0.f, ry1 = 0.f;
#pragma unroll 8
    for (int d = 0; d < 64; ++d) {
        float qx = s_q[warp][d], qy = s_q[warp][64 + d];
        rx0 += qx * keys[d * 64 + lane];
        rx1 += qx * keys[d * 64 + lane + 32];
        ry0 += qy * keys[4096 + d * 64 + lane];
        ry1 += qy * keys[4096 + d * 64 + lane + 32];
    }

#pragma unroll 1
    for (int r = 0; r < 8; ++r) {
        float v; int i;
        if (rx0 >= rx1) { v = rx0; i = lane; } else { v = rx1; i = lane + 32; }
#pragma unroll
        for (int s = 16; s; s >>= 1) {
            float ov = __shfl_xor_sync(0xffffffffu, v, s);
            int   oi = __shfl_xor_sync(0xffffffffu, i, s);
            if (ov > v || (ov == v && oi < i)) { v = ov; i = oi; }
        }
        if (lane == 0) { s_tsx[warp][r] = v; s_tix[warp][r] = i; }
        if (i == lane)      rx0 = -INFINITY;
        if (i == lane + 32) rx1 = -INFINITY;
    }
#pragma unroll 1
    for (int r = 0; r < 8; ++r) {
        float v; int i;
        if (ry0 >= ry1) { v = ry0; i = lane; } else { v = ry1; i = lane + 32; }
#pragma unroll
        for (int s = 16; s; s >>= 1) {
            float ov = __shfl_xor_sync(0xffffffffu, v, s);
            int   oi = __shfl_xor_sync(0xffffffffu, i, s);
            if (ov > v || (ov == v && oi < i)) { v = ov; i = oi; }
        }
        if (lane == 0) { s_tsy[warp][r] = v; s_tiy[warp][r] = i; }
        if (i == lane)      ry0 = -INFINITY;
        if (i == lane + 32) ry1 = -INFINITY;
    }
    __syncwarp();

    float c0 = s_tsx[warp][lane >> 3]        + s_tsy[warp][lane & 7];
    float c1 = s_tsx[warp][(lane + 32) >> 3] + s_tsy[warp][(lane + 32) & 7];
#pragma unroll 1
    for (int r = 0; r < 8; ++r) {
        float v; int p;
        if (c0 >= c1) { v = c0; p = lane; } else { v = c1; p = lane + 32; }
#pragma unroll
        for (int s = 16; s; s >>= 1) {
            float ov = __shfl_xor_sync(0xffffffffu, v, s);
            int   op = __shfl_xor_sync(0xffffffffu, p, s);
            if (ov > v || (ov == v && op < p)) { v = ov; p = op; }
        }
        if (lane == 0) { s_sel[warp][r] = v; s_pos[warp][r] = p; }
        if (p == lane)      c0 = -INFINITY;
        if (p == lane + 32) c1 = -INFINITY;
    }
    __syncwarp();

    if (lane < 8) {
        float mx = s_sel[warp][0];
        float e  = expf(s_sel[warp][lane] - mx);
        float sum = e;
#pragma unroll
        for (int s = 4; s; s >>= 1) sum += __shfl_xor_sync(0xffu, sum, s);
        int p  = s_pos[warp][lane];
        int ex = s_tix[warp][p >> 3] * 64 + s_tiy[warp][p & 7];
        eidx[m * TOPK + lane]  = ex;
        probs[m * TOPK + lane] = e / sum;
    }
}

// ---------------- per-token expert compute (adds into d_out) ----------------
__global__ void __launch_bounds__(256)
expert_kernel(const float* __restrict__ x, const float* __restrict__ down_embed,
              const float* __restrict__ up_embed, const int* __restrict__ eidx,
              const float* __restrict__ probs, float* __restrict__ out)
{
    const int n = blockIdx.x;
    __shared__ __align__(16) float sx[HID];
    __shared__ float coeff[TOPK];
    __shared__ int   se[TOPK];

    const int tid = threadIdx.x;
    const float4* xin = (const float4*)(x + (size_t)n * HID);
    float4* sx4 = (float4*)sx;
    sx4[tid]       = xin[tid];
    sx4[tid + 256] = xin[tid + 256];
    if (tid < TOPK) se[tid] = eidx[n * TOPK + tid];
    __syncthreads();

    const int w = tid >> 5, lane = tid & 31;
    {
        const float* de = down_embed + (size_t)se[w] * HID;
        float acc = 0.f;
#pragma unroll
        for (int i = 0; i < 64; ++i) acc += sx[i * 32 + lane] * de[i * 32 + lane];
#pragma unroll
        for (int s = 16; s; s >>= 1) acc += __shfl_xor_sync(0xffffffffu, acc, s);
        if (lane == 0)
            coeff[w] = acc / (1.f + expf(-acc)) * probs[n * TOPK + w];
    }
    __syncthreads();

    float cc[TOPK]; int ee[TOPK];
#pragma unroll
    for (int k = 0; k < TOPK; ++k) { cc[k] = coeff[k]; ee[k] = se[k]; }

#pragma unroll
    for (int h = tid; h < HID; h += 256) {
        float acc = out[(size_t)n * HID + h];
#pragma unroll
        for (int k = 0; k < TOPK; ++k)
            acc += cc[k] * up_embed[(size_t)ee[k] * HID + h];
        out[(size_t)n * HID + h] = acc;
    }
}

// ---------------- launch ----------------
extern "C" void kernel_launch(void* const* d_in, const int* in_sizes, int n_in,
                              void* d_out, int out_size) {
    (void)in_sizes; (void)n_in; (void)out_size;
    const float* x    = (const float*)d_in[0];
    const float* Wq   = (const float*)d_in[1];
    const float* keys = (const float*)d_in[2];
    const float* de   = (const float*)d_in[3];
    const float* ue   = (const float*)d_in[4];
    const float* gw   = (const float*)d_in[5];
    const float* uw   = (const float*)d_in[6];
    const float* dw   = (const float*)d_in[7];
    float* out = (float*)d_out;

    void *xh, *xl, *wqh, *wql, *gwh, *gwl, *uwh, *uwl, *dwh, *dwl;
    void *Gp, *hh, *hl, *Qp, *idxp, *pp;
    cudaGetSymbolAddress(&xh,  g_x_hi);  cudaGetSymbolAddress(&xl,  g_x_lo);
    cudaGetSymbolAddress(&wqh, g_wq_hi); cudaGetSymbolAddress(&wql, g_wq_lo);
    cudaGetSymbolAddress(&gwh, g_gw_hi); cudaGetSymbolAddress(&gwl, g_gw_lo);
    cudaGetSymbolAddress(&uwh, g_uw_hi); cudaGetSymbolAddress(&uwl, g_uw_lo);
    cudaGetSymbolAddress(&dwh, g_dw_hi); cudaGetSymbolAddress(&dwl, g_dw_lo);
    cudaGetSymbolAddress(&Gp,  g_G);
    cudaGetSymbolAddress(&hh,  g_h_hi);  cudaGetSymbolAddress(&hl,  g_h_lo);
    cudaGetSymbolAddress(&Qp,  g_Q);
    cudaGetSymbolAddress(&idxp, g_eidx); cudaGetSymbolAddress(&pp, g_prob);

    const int SMEM = 3 * 58368;   // 175104 B
    cudaFuncSetAttribute(gemm3x_kernel, cudaFuncAttributeMaxDynamicSharedMemorySize, SMEM);

    // launches 0-4: splits
    split_kernel<<<2048, 256>>>(x,  (bf16*)xh,  (bf16*)xl,  NTOK * HID);
    split_kernel<<<256,  256>>>(Wq, (bf16*)wqh, (bf16*)wql, HID * RET);
    split_kernel<<<2048, 256>>>(gw, (bf16*)gwh, (bf16*)gwl, HID * INTER);
    split_kernel<<<2048, 256>>>(uw, (bf16*)uwh, (bf16*)uwl, HID * INTER);
    split_kernel<<<2048, 256>>>(dw, (bf16*)dwh, (bf16*)dwl, INTER * HID);

    // launch 5 (ncu profiles this one): G = x @ gate_w
    gemm3x_kernel<<<dim3(INTER / 128, NTOK / 256), 256, SMEM>>>(
        (const bf16*)xh, (const bf16*)xl, (const bf16*)gwh, (const bf16*)gwl,
        NTOK, INTER, HID, (float*)Gp, nullptr, nullptr, nullptr, 0);

    // U = x @ up_w, fused: h = silu(G)*U -> (h_hi, h_lo)
    gemm3x_kernel<<<dim3(INTER / 128, NTOK / 256), 256, SMEM>>>(
        (const bf16*)xh, (const bf16*)xl, (const bf16*)uwh, (const bf16*)uwl,
        NTOK, INTER, HID, nullptr, (const float*)Gp, (bf16*)hh, (bf16*)hl, 1);

    // Q = x @ W_q
    gemm3x_kernel<<<dim3(1, NTOK / 256), 256, SMEM>>>(
        (const bf16*)xh, (const bf16*)xl, (const bf16*)wqh, (const bf16*)wql,
        NTOK, RET, HID, (float*)Qp, nullptr, nullptr, nullptr, 0);

    // routing
    routing_kernel<<<NTOK / 8, 256>>>((const float*)Qp, keys, (int*)idxp, (float*)pp);

    // out = h @ down_w
    gemm3x_kernel<<<dim3(HID / 128, NTOK / 256), 256, SMEM>>>(
        (const bf16*)hh, (const bf16*)hl, (const bf16*)dwh, (const bf16*)dwl,
        NTOK, HID, INTER, out, nullptr, nullptr, nullptr, 0);

    // experts: out += sum_k silu(x·de_k)*softmax_k * ue_k
    expert_kernel<<<NTOK, 256>>>(x, de, ue, (const int*)idxp, (const float*)pp, out);
}

// round 9
// speedup vs baseline: 2.0822x; 2.0518x over previous
#include <cuda_runtime.h>
#include <cuda_bf16.h>
#include <cuda_fp16.h>
#include <math.h>
#include <stdint.h>

using bf16 = __nv_bfloat16;

// ---------------- problem constants ----------------
#define NTOK  8192     // B*S
#define HID   2048
#define INTER 8192
#define RET   128
#define TOPK  8

// ---------------- scratch (__device__ globals; no allocation allowed) ----------------
__device__ __align__(256) __half g_x16[(size_t)NTOK * HID];
__device__ __align__(256) __half g_gw16[(size_t)HID * INTER];
__device__ __align__(256) __half g_uw16[(size_t)HID * INTER];
__device__ __align__(256) __half g_dw16[(size_t)INTER * HID];
__device__ __align__(256) __half g_G16[(size_t)NTOK * INTER];    // gate pre-act (fp16)
__device__ __align__(256) __half g_h16[(size_t)NTOK * INTER];    // silu(g)*u (fp16)
__device__ __align__(256) bf16  g_x_hi[(size_t)NTOK * HID];      // Q path (bf16x3)
__device__ __align__(256) bf16  g_x_lo[(size_t)NTOK * HID];
__device__ __align__(256) bf16  g_wq_hi[HID * RET];
__device__ __align__(256) bf16  g_wq_lo[HID * RET];
__device__ __align__(256) float g_Q[NTOK * RET];
__device__ __align__(256) int   g_eidx[NTOK * TOPK];
__device__ __align__(256) float g_prob[NTOK * TOPK];

// ---------------- helpers ----------------
__device__ __forceinline__ void cp16(uint32_t s, const void* g) {
    asm volatile("cp.async.cg.shared.global [%0], [%1], 16;\n" :: "r"(s), "l"(g));
}
#define CP_COMMIT() asm volatile("cp.async.commit_group;\n" ::: "memory")
#define CP_WAIT1()  asm volatile("cp.async.wait_group 1;\n" ::: "memory")
#define CP_WAIT0()  asm volatile("cp.async.wait_group 0;\n" ::: "memory")

__device__ __forceinline__ void ldsm_x4(uint32_t (&r)[4], uint32_t addr) {
    asm volatile("ldmatrix.sync.aligned.m8n8.x4.shared.b16 {%0,%1,%2,%3}, [%4];"
                 : "=r"(r[0]), "=r"(r[1]), "=r"(r[2]), "=r"(r[3]) : "r"(addr));
}
__device__ __forceinline__ void ldsm_x4t(uint32_t (&r)[4], uint32_t addr) {
    asm volatile("ldmatrix.sync.aligned.m8n8.x4.trans.shared.b16 {%0,%1,%2,%3}, [%4];"
                 : "=r"(r[0]), "=r"(r[1]), "=r"(r[2]), "=r"(r[3]) : "r"(addr));
}
__device__ __forceinline__ void mma_bf(float (&c)[4], const uint32_t (&a)[4], const uint32_t (&b)[2]) {
    asm volatile("mma.sync.aligned.m16n8k16.row.col.f32.bf16.bf16.f32 "
                 "{%0,%1,%2,%3},{%4,%5,%6,%7},{%8,%9},{%0,%1,%2,%3};"
                 : "+f"(c[0]), "+f"(c[1]), "+f"(c[2]), "+f"(c[3])
                 : "r"(a[0]), "r"(a[1]), "r"(a[2]), "r"(a[3]), "r"(b[0]), "r"(b[1]));
}
__device__ __forceinline__ void mma_fp(float (&c)[4], const uint32_t (&a)[4], const uint32_t (&b)[2]) {
    asm volatile("mma.sync.aligned.m16n8k16.row.col.f32.f16.f16.f32 "
                 "{%0,%1,%2,%3},{%4,%5,%6,%7},{%8,%9},{%0,%1,%2,%3};"
                 : "+f"(c[0]), "+f"(c[1]), "+f"(c[2]), "+f"(c[3])
                 : "r"(a[0]), "r"(a[1]), "r"(a[2]), "r"(a[3]), "r"(b[0]), "r"(b[1]));
}

// ---------------- fp32 -> fp16 convert ----------------
__global__ void cvt16_kernel(const float* __restrict__ in, __half* __restrict__ o, int n) {
    int i = blockIdx.x * blockDim.x + threadIdx.x;
    int stride = gridDim.x * blockDim.x;
    for (; i < n; i += stride) o[i] = __float2half(in[i]);
}

// ---------------- combined bf16 hi/lo splits for the Q path (x and W_q) ----------------
__global__ void splitq_kernel(const float* __restrict__ a, bf16* __restrict__ ah, bf16* __restrict__ al, int n1,
                              const float* __restrict__ b, bf16* __restrict__ bh, bf16* __restrict__ bl, int n2) {
    int i = blockIdx.x * blockDim.x + threadIdx.x;
    int stride = gridDim.x * blockDim.x;
    for (; i < n1 + n2; i += stride) {
        if (i < n1) {
            float v = a[i];
            bf16 h = __float2bfloat16(v);
            ah[i] = h;
            al[i] = __float2bfloat16(v - __bfloat162float(h));
        } else {
            int j = i - n1;
            float v = b[j];
            bf16 h = __float2bfloat16(v);
            bh[j] = h;
            bl[j] = __float2bfloat16(v - __bfloat162float(h));
        }
    }
}

// ============================================================================
// Single-pass fp16 GEMM: C = A*B. A row-major [M,K], B row-major [K,N].
// CTA tile 256x128x32, 256 threads, warp grid 4(m)x2(n), warp tile 64x64,
// 3-stage cp.async pipeline.
// mode 0: Cout(fp32)=acc ; mode 1: Hout(fp16)=silu(Gin)*acc ; mode 2: Hout(fp16)=acc
// ============================================================================
#define HASTG   20480u
#define HSTAGEB 29184u

__global__ void __launch_bounds__(256, 1)
gemmh_kernel(const __half* __restrict__ A, const __half* __restrict__ B,
             int M, int N, int K,
             float* __restrict__ Cout, const __half* __restrict__ Gin,
             __half* __restrict__ Hout, int mode)
{
    extern __shared__ __align__(16) unsigned char smem_raw[];
    const uint32_t sb = (uint32_t)__cvta_generic_to_shared(smem_raw);

    const int tid  = threadIdx.x;
    const int lane = tid & 31;
    const int warp = tid >> 5;
    const int wm   = warp >> 1;   // 0..3
    const int wn   = warp & 1;    // 0..1
    const int mBlk = blockIdx.y * 256;
    const int nBlk = blockIdx.x * 128;
    const int KT   = K >> 5;

    float c[4][8][4];
#pragma unroll
    for (int i = 0; i < 4; i++)
#pragma unroll
        for (int j = 0; j < 8; j++)
#pragma unroll
            for (int k = 0; k < 4; k++) c[i][j][k] = 0.f;

    auto load_stage = [&](int st, int kt) {
        const int k0 = kt << 5;
        const uint32_t base = sb + (uint32_t)st * HSTAGEB;
#pragma unroll
        for (int r = 0; r < 4; ++r) {                  // A: 1024 chunks (256 rows x 4 segs)
            int id = tid + r * 256;
            int row = id >> 2, seg = id & 3;
            size_t go = (size_t)(mBlk + row) * K + k0 + seg * 8;
            cp16(base + (uint32_t)row * 80u + (uint32_t)seg * 16u, A + go);
        }
#pragma unroll
        for (int r = 0; r < 2; ++r) {                  // B: 512 chunks (32 rows x 16 segs)
            int id = tid + r * 256;
            int row = id >> 4, seg = id & 15;
            size_t go = (size_t)(k0 + row) * N + nBlk + seg * 8;
            cp16(base + HASTG + (uint32_t)row * 272u + (uint32_t)seg * 16u, B + go);
        }
    };

    load_stage(0, 0); CP_COMMIT();
    load_stage(1, 1); CP_COMMIT();

    int st = 0;
    for (int kt = 0; kt < KT; ++kt) {
        if (kt + 2 < KT) CP_WAIT1(); else CP_WAIT0();
        __syncthreads();
        if (kt + 2 < KT) {
            int st2 = st + 2; if (st2 >= 3) st2 -= 3;
            load_stage(st2, kt + 2);
            CP_COMMIT();
        }
        const uint32_t base = sb + (uint32_t)st * HSTAGEB;
#pragma unroll
        for (int kk = 0; kk < 2; ++kk) {
            const uint32_t acol = (uint32_t)(kk * 16 + (lane >> 4) * 8) * 2u;
            const uint32_t brow = base + HASTG + (uint32_t)(kk * 16 + (lane & 15)) * 272u;

            uint32_t a[4][4], b[8][2];
#pragma unroll
            for (int mi = 0; mi < 4; mi++)
                ldsm_x4(a[mi], base + (uint32_t)(wm * 64 + mi * 16 + (lane & 15)) * 80u + acol);
#pragma unroll
            for (int nj = 0; nj < 4; nj++) {
                uint32_t r[4];
                ldsm_x4t(r, brow + (uint32_t)(wn * 64 + nj * 16 + (lane >> 4) * 8) * 2u);
                b[2*nj][0] = r[0]; b[2*nj][1] = r[1];
                b[2*nj+1][0] = r[2]; b[2*nj+1][1] = r[3];
            }
#pragma unroll
            for (int mi = 0; mi < 4; mi++)
#pragma unroll
                for (int nt = 0; nt < 8; nt++) mma_fp(c[mi][nt], a[mi], b[nt]);
        }
        ++st; if (st >= 3) st = 0;
    }

    // epilogue
#pragma unroll
    for (int mi = 0; mi < 4; mi++) {
#pragma unroll
        for (int nt = 0; nt < 8; nt++) {
            int row = mBlk + wm * 64 + mi * 16 + (lane >> 2);
            int col = nBlk + wn * 64 + nt * 8 + (lane & 3) * 2;
#pragma unroll
            for (int hrow = 0; hrow < 2; ++hrow) {
                int r = row + hrow * 8;
                size_t i0 = (size_t)r * N + col;
                float v0 = c[mi][nt][hrow * 2 + 0];
                float v1 = c[mi][nt][hrow * 2 + 1];
                if (mode == 0) {
                    Cout[i0]     = v0;
                    Cout[i0 + 1] = v1;
                } else if (mode == 1) {
                    float gg0 = __half2float(Gin[i0]), gg1 = __half2float(Gin[i0 + 1]);
                    float hv0 = gg0 / (1.f + expf(-gg0)) * v0;
                    float hv1 = gg1 / (1.f + expf(-gg1)) * v1;
                    Hout[i0]     = __float2half(hv0);
                    Hout[i0 + 1] = __float2half(hv1);
                } else {
                    Hout[i0]     = __float2half(v0);
                    Hout[i0 + 1] = __float2half(v1);
                }
            }
        }
    }
}

// ============================================================================
// bf16x3 GEMM for the Q projection (protects top-k routing). Proven structure.
// ============================================================================
#define ASTG   20480u
#define BSTG   8704u
#define STAGEB 58368u

__global__ void __launch_bounds__(256, 1)
gemm3x_kernel(const bf16* __restrict__ Ah, const bf16* __restrict__ Al,
              const bf16* __restrict__ Bh, const bf16* __restrict__ Bl,
              int M, int N, int K, float* __restrict__ Cout)
{
    extern __shared__ __align__(16) unsigned char smem_raw[];
    const uint32_t sb = (uint32_t)__cvta_generic_to_shared(smem_raw);

    const int tid  = threadIdx.x;
    const int lane = tid & 31;
    const int warp = tid >> 5;
    const int wm   = warp >> 1;
    const int wn   = warp & 1;
    const int mBlk = blockIdx.y * 256;
    const int nBlk = blockIdx.x * 128;
    const int KT   = K >> 5;

    float c[4][8][4];
#pragma unroll
    for (int i = 0; i < 4; i++)
#pragma unroll
        for (int j = 0; j < 8; j++)
#pragma unroll
            for (int k = 0; k < 4; k++) c[i][j][k] = 0.f;

    auto load_stage = [&](int st, int kt) {
        const int k0 = kt << 5;
        const uint32_t base = sb + (uint32_t)st * STAGEB;
#pragma unroll
        for (int r = 0; r < 4; ++r) {
            int id = tid + r * 256;
            int row = id >> 2, seg = id & 3;
            size_t go = (size_t)(mBlk + row) * K + k0 + seg * 8;
            uint32_t so = base + (uint32_t)row * 80u + (uint32_t)seg * 16u;
            cp16(so, Ah + go);
            cp16(so + ASTG, Al + go);
        }
#pragma unroll
        for (int r = 0; r < 2; ++r) {
            int id = tid + r * 256;
            int row = id >> 4, seg = id & 15;
            size_t go = (size_t)(k0 + row) * N + nBlk + seg * 8;
            uint32_t so = base + 2 * ASTG + (uint32_t)row * 272u + (uint32_t)seg * 16u;
            cp16(so, Bh + go);
            cp16(so + BSTG, Bl + go);
        }
    };

    load_stage(0, 0); CP_COMMIT();
    load_stage(1, 1); CP_COMMIT();

    int st = 0;
    for (int kt = 0; kt < KT; ++kt) {
        if (kt + 2 < KT) CP_WAIT1(); else CP_WAIT0();
        __syncthreads();
        if (kt + 2 < KT) {
            int st2 = st + 2; if (st2 >= 3) st2 -= 3;
            load_stage(st2, kt + 2);
            CP_COMMIT();
        }
        const uint32_t base = sb + (uint32_t)st * STAGEB;
#pragma unroll
        for (int kk = 0; kk < 2; ++kk) {
            const uint32_t acol = (uint32_t)(kk * 16 + (lane >> 4) * 8) * 2u;
            const uint32_t brow = base + 2 * ASTG + (uint32_t)(kk * 16 + (lane & 15)) * 272u;

            uint32_t ah[4][4], bh[8][2];
#pragma unroll
            for (int mi = 0; mi < 4; mi++)
                ldsm_x4(ah[mi], base + (uint32_t)(wm * 64 + mi * 16 + (lane & 15)) * 80u + acol);
#pragma unroll
            for (int nj = 0; nj < 4; nj++) {
                uint32_t r[4];
                ldsm_x4t(r, brow + (uint32_t)(wn * 64 + nj * 16 + (lane >> 4) * 8) * 2u);
                bh[2*nj][0] = r[0]; bh[2*nj][1] = r[1];
                bh[2*nj+1][0] = r[2]; bh[2*nj+1][1] = r[3];
            }
#pragma unroll
            for (int mi = 0; mi < 4; mi++)
#pragma unroll
                for (int nt = 0; nt < 8; nt++) mma_bf(c[mi][nt], ah[mi], bh[nt]);

            uint32_t al[4][4];
#pragma unroll
            for (int mi = 0; mi < 4; mi++)
                ldsm_x4(al[mi], base + ASTG + (uint32_t)(wm * 64 + mi * 16 + (lane & 15)) * 80u + acol);
#pragma unroll
            for (int mi = 0; mi < 4; mi++)
#pragma unroll
                for (int nt = 0; nt < 8; nt++) mma_bf(c[mi][nt], al[mi], bh[nt]);

            uint32_t bl[8][2];
#pragma unroll
            for (int nj = 0; nj < 4; nj++) {
                uint32_t r[4];
                ldsm_x4t(r, brow + BSTG + (uint32_t)(wn * 64 + nj * 16 + (lane >> 4) * 8) * 2u);
                bl[2*nj][0] = r[0]; bl[2*nj][1] = r[1];
                bl[2*nj+1][0] = r[2]; bl[2*nj+1][1] = r[3];
            }
#pragma unroll
            for (int mi = 0; mi < 4; mi++)
#pragma unroll
                for (int nt = 0; nt < 8; nt++) mma_bf(c[mi][nt], ah[mi], bl[nt]);
        }
        ++st; if (st >= 3) st = 0;
    }

#pragma unroll
    for (int mi = 0; mi < 4; mi++)
#pragma unroll
        for (int nt = 0; nt < 8; nt++) {
            int row = mBlk + wm * 64 + mi * 16 + (lane >> 2);
            int col = nBlk + wn * 64 + nt * 8 + (lane & 3) * 2;
#pragma unroll
            for (int hrow = 0; hrow < 2; ++hrow) {
                int r = row + hrow * 8;
                size_t i0 = (size_t)r * N + col;
                Cout[i0]     = c[mi][nt][hrow * 2 + 0];
                Cout[i0 + 1] = c[mi][nt][hrow * 2 + 1];
            }
        }
}

// ---------------- product-key routing: top8 x top8 -> top8, softmax ----------------
__global__ void __launch_bounds__(256)
routing_kernel(const float* __restrict__ Q, const float* __restrict__ keys,
               int* __restrict__ eidx, float* __restrict__ probs)
{
    const int warp = threadIdx.x >> 5, lane = threadIdx.x & 31;
    const int m = blockIdx.x * 8 + warp;

    __shared__ float s_q[8][128];
    __shared__ float s_tsx[8][8], s_tsy[8][8];
    __shared__ int   s_tix[8][8], s_tiy[8][8];
    __shared__ float s_sel[8][8];
    __shared__ int   s_pos[8][8];

    const int j0 = (m >> 1);
    const int j1 = 4096 + (m >> 1);
    const int o  = (m & 1) * 64;
    s_q[warp][lane]           = Q[j0 * RET + o + lane];
    s_q[warp][lane + 32]      = Q[j0 * RET + o + lane + 32];
    s_q[warp][64 + lane]      = Q[j1 * RET + o + lane];
    s_q[warp][64 + lane + 32] = Q[j1 * RET + o + lane + 32];
    __syncwarp();

    float rx0 = 0.f, rx1 = 0.f, ry0 = 0.f, ry1 = 0.f;
#pragma unroll 8
    for (int d = 0; d < 64; ++d) {
        float qx = s_q[warp][d], qy = s_q[warp][64 + d];
        rx0 += qx * keys[d * 64 + lane];
        rx1 += qx * keys[d * 64 + lane + 32];
        ry0 += qy * keys[4096 + d * 64 + lane];
        ry1 += qy * keys[4096 + d * 64 + lane + 32];
    }

#pragma unroll 1
    for (int r = 0; r < 8; ++r) {
        float v; int i;
        if (rx0 >= rx1) { v = rx0; i = lane; } else { v = rx1; i = lane + 32; }
#pragma unroll
        for (int s = 16; s; s >>= 1) {
            float ov = __shfl_xor_sync(0xffffffffu, v, s);
            int   oi = __shfl_xor_sync(0xffffffffu, i, s);
            if (ov > v || (ov == v && oi < i)) { v = ov; i = oi; }
        }
        if (lane == 0) { s_tsx[warp][r] = v; s_tix[warp][r] = i; }
        if (i == lane)      rx0 = -INFINITY;
        if (i == lane + 32) rx1 = -INFINITY;
    }
#pragma unroll 1
    for (int r = 0; r < 8; ++r) {
        float v; int i;
        if (ry0 >= ry1) { v = ry0; i = lane; } else { v = ry1; i = lane + 32; }
#pragma unroll
        for (int s = 16; s; s >>= 1) {
            float ov = __shfl_xor_sync(0xffffffffu, v, s);
            int   oi = __shfl_xor_sync(0xffffffffu, i, s);
            if (ov > v || (ov == v && oi < i)) { v = ov; i = oi; }
        }
        if (lane == 0) { s_tsy[warp][r] = v; s_tiy[warp][r] = i; }
        if (i == lane)      ry0 = -INFINITY;
        if (i == lane + 32) ry1 = -INFINITY;
    }
    __syncwarp();

    float c0 = s_tsx[warp][lane >> 3]        + s_tsy[warp][lane & 7];
    float c1 = s_tsx[warp][(lane + 32) >> 3] + s_tsy[warp][(lane + 32) & 7];
#pragma unroll 1
    for (int r = 0; r < 8; ++r) {
        float v; int p;
        if (c0 >= c1) { v = c0; p = lane; } else { v = c1; p = lane + 32; }
#pragma unroll
        for (int s = 16; s; s >>= 1) {
            float ov = __shfl_xor_sync(0xffffffffu, v, s);
            int   op = __shfl_xor_sync(0xffffffffu, p, s);
            if (ov > v || (ov == v && op < p)) { v = ov; p = op; }
        }
        if (lane == 0) { s_sel[warp][r] = v; s_pos[warp][r] = p; }
        if (p == lane)      c0 = -INFINITY;
        if (p == lane + 32) c1 = -INFINITY;
    }
    __syncwarp();

    if (lane < 8) {
        float mx = s_sel[warp][0];
        float e  = expf(s_sel[warp][lane] - mx);
        float sum = e;
#pragma unroll
        for (int s = 4; s; s >>= 1) sum += __shfl_xor_sync(0xffu, sum, s);
        int p  = s_pos[warp][lane];
        int ex = s_tix[warp][p >> 3] * 64 + s_tiy[warp][p & 7];
        eidx[m * TOPK + lane]  = ex;
        probs[m * TOPK + lane] = e / sum;
    }
}

// ---------------- per-token expert compute (adds into d_out) ----------------
__global__ void __launch_bounds__(256)
expert_kernel(const float* __restrict__ x, const float* __restrict__ down_embed,
              const float* __restrict__ up_embed, const int* __restrict__ eidx,
              const float* __restrict__ probs, float* __restrict__ out)
{
    const int n = blockIdx.x;
    __shared__ __align__(16) float sx[HID];
    __shared__ float coeff[TOPK];
    __shared__ int   se[TOPK];

    const int tid = threadIdx.x;
    const float4* xin = (const float4*)(x + (size_t)n * HID);
    float4* sx4 = (float4*)sx;
    sx4[tid]       = xin[tid];
    sx4[tid + 256] = xin[tid + 256];
    if (tid < TOPK) se[tid] = eidx[n * TOPK + tid];
    __syncthreads();

    const int w = tid >> 5, lane = tid & 31;
    {
        const float* de = down_embed + (size_t)se[w] * HID;
        float acc = 0.f;
#pragma unroll
        for (int i = 0; i < 64; ++i) acc += sx[i * 32 + lane] * de[i * 32 + lane];
#pragma unroll
        for (int s = 16; s; s >>= 1) acc += __shfl_xor_sync(0xffffffffu, acc, s);
        if (lane == 0)
            coeff[w] = acc / (1.f + expf(-acc)) * probs[n * TOPK + w];
    }
    __syncthreads();

    float cc[TOPK]; int ee[TOPK];
#pragma unroll
    for (int k = 0; k < TOPK; ++k) { cc[k] = coeff[k]; ee[k] = se[k]; }

#pragma unroll
    for (int h = tid; h < HID; h += 256) {
        float acc = out[(size_t)n * HID + h];
#pragma unroll
        for (int k = 0; k < TOPK; ++k)
            acc += cc[k] * up_embed[(size_t)ee[k] * HID + h];
        out[(size_t)n * HID + h] = acc;
    }
}

// ---------------- launch ----------------
extern "C" void kernel_launch(void* const* d_in, const int* in_sizes, int n_in,
                              void* d_out, int out_size) {
    (void)in_sizes; (void)n_in; (void)out_size;
    const float* x    = (const float*)d_in[0];
    const float* Wq   = (const float*)d_in[1];
    const float* keys = (const float*)d_in[2];
    const float* de   = (const float*)d_in[3];
    const float* ue   = (const float*)d_in[4];
    const float* gw   = (const float*)d_in[5];
    const float* uw   = (const float*)d_in[6];
    const float* dw   = (const float*)d_in[7];
    float* out = (float*)d_out;

    void *x16, *gw16, *uw16, *dw16, *G16, *h16;
    void *xh, *xl, *wqh, *wql, *Qp, *idxp, *pp;
    cudaGetSymbolAddress(&x16,  g_x16);   cudaGetSymbolAddress(&gw16, g_gw16);
    cudaGetSymbolAddress(&uw16, g_uw16);  cudaGetSymbolAddress(&dw16, g_dw16);
    cudaGetSymbolAddress(&G16,  g_G16);   cudaGetSymbolAddress(&h16,  g_h16);
    cudaGetSymbolAddress(&xh,   g_x_hi);  cudaGetSymbolAddress(&xl,   g_x_lo);
    cudaGetSymbolAddress(&wqh,  g_wq_hi); cudaGetSymbolAddress(&wql,  g_wq_lo);
    cudaGetSymbolAddress(&Qp,   g_Q);
    cudaGetSymbolAddress(&idxp, g_eidx);  cudaGetSymbolAddress(&pp,   g_prob);

    const int SMEM_H  = 3 * 29184;   // 87552
    const int SMEM_3X = 3 * 58368;   // 175104
    cudaFuncSetAttribute(gemmh_kernel,  cudaFuncAttributeMaxDynamicSharedMemorySize, SMEM_H);
    cudaFuncSetAttribute(gemm3x_kernel, cudaFuncAttributeMaxDynamicSharedMemorySize, SMEM_3X);

    // launches 0-4: conversions + Q-path splits
    cvt16_kernel<<<2048, 256>>>(x,  (__half*)x16,  NTOK * HID);
    cvt16_kernel<<<2048, 256>>>(gw, (__half*)gw16, HID * INTER);
    cvt16_kernel<<<2048, 256>>>(uw, (__half*)uw16, HID * INTER);
    cvt16_kernel<<<2048, 256>>>(dw, (__half*)dw16, INTER * HID);
    splitq_kernel<<<2048, 256>>>(x, (bf16*)xh, (bf16*)xl, NTOK * HID,
                                 Wq, (bf16*)wqh, (bf16*)wql, HID * RET);

    // launch 5 (ncu target): G = x @ gate_w -> fp16
    gemmh_kernel<<<dim3(INTER / 128, NTOK / 256), 256, SMEM_H>>>(
        (const __half*)x16, (const __half*)gw16, NTOK, INTER, HID,
        nullptr, nullptr, (__half*)G16, 2);

    // U = x @ up_w fused: h = silu(G)*U -> fp16
    gemmh_kernel<<<dim3(INTER / 128, NTOK / 256), 256, SMEM_H>>>(
        (const __half*)x16, (const __half*)uw16, NTOK, INTER, HID,
        nullptr, (const __half*)G16, (__half*)h16, 1);

    // Q = x @ W_q (bf16x3)
    gemm3x_kernel<<<dim3(1, NTOK / 256), 256, SMEM_3X>>>(
        (const bf16*)xh, (const bf16*)xl, (const bf16*)wqh, (const bf16*)wql,
        NTOK, RET, HID, (float*)Qp);

    // routing
    routing_kernel<<<NTOK / 8, 256>>>((const float*)Qp, keys, (int*)idxp, (float*)pp);

    // out = h @ down_w (fp32)
    gemmh_kernel<<<dim3(HID / 128, NTOK / 256), 256, SMEM_H>>>(
        (const __half*)h16, (const __half*)dw16, NTOK, HID, INTER,
        out, nullptr, nullptr, 0);

    // experts: out += sum_k silu(x·de_k)*softmax_k * ue_k
    expert_kernel<<<NTOK, 256>>>(x, de, ue, (const int*)idxp, (const float*)pp, out);
}

// round 10
// speedup vs baseline: 2.1893x; 1.0515x over previous
#include <cuda_runtime.h>
#include <cuda_bf16.h>
#include <cuda_fp16.h>
#include <math.h>
#include <stdint.h>

using bf16 = __nv_bfloat16;

// ---------------- problem constants ----------------
#define NTOK  8192     // B*S
#define HID   2048
#define INTER 8192
#define RET   128
#define TOPK  8

// ---------------- scratch (__device__ globals; no allocation allowed) ----------------
__device__ __align__(256) __half g_x16[(size_t)NTOK * HID];
__device__ __align__(256) __half g_gw16[(size_t)HID * INTER];
__device__ __align__(256) __half g_uw16[(size_t)HID * INTER];
__device__ __align__(256) __half g_dw16[(size_t)INTER * HID];
__device__ __align__(256) __half g_G16[(size_t)NTOK * INTER];    // gate pre-act (fp16)
__device__ __align__(256) __half g_h16[(size_t)NTOK * INTER];    // silu(g)*u (fp16)
__device__ __align__(256) bf16  g_x_hi[(size_t)NTOK * HID];      // Q path (bf16x3)
__device__ __align__(256) bf16  g_x_lo[(size_t)NTOK * HID];
__device__ __align__(256) bf16  g_wq_hi[HID * RET];
__device__ __align__(256) bf16  g_wq_lo[HID * RET];
__device__ __align__(256) float g_Q[NTOK * RET];
__device__ __align__(256) int   g_eidx[NTOK * TOPK];
__device__ __align__(256) float g_prob[NTOK * TOPK];
__device__ __align__(256) float g_es[(size_t)NTOK * HID];        // expert states

// ---------------- helpers ----------------
__device__ __forceinline__ void cp16(uint32_t s, const void* g) {
    asm volatile("cp.async.cg.shared.global [%0], [%1], 16;\n" :: "r"(s), "l"(g));
}
#define CP_COMMIT() asm volatile("cp.async.commit_group;\n" ::: "memory")
#define CP_WAIT1()  asm volatile("cp.async.wait_group 1;\n" ::: "memory")
#define CP_WAIT0()  asm volatile("cp.async.wait_group 0;\n" ::: "memory")

__device__ __forceinline__ void ldsm_x4(uint32_t (&r)[4], uint32_t addr) {
    asm volatile("ldmatrix.sync.aligned.m8n8.x4.shared.b16 {%0,%1,%2,%3}, [%4];"
                 : "=r"(r[0]), "=r"(r[1]), "=r"(r[2]), "=r"(r[3]) : "r"(addr));
}
__device__ __forceinline__ void ldsm_x4t(uint32_t (&r)[4], uint32_t addr) {
    asm volatile("ldmatrix.sync.aligned.m8n8.x4.trans.shared.b16 {%0,%1,%2,%3}, [%4];"
                 : "=r"(r[0]), "=r"(r[1]), "=r"(r[2]), "=r"(r[3]) : "r"(addr));
}
__device__ __forceinline__ void mma_bf(float (&c)[4], const uint32_t (&a)[4], const uint32_t (&b)[2]) {
    asm volatile("mma.sync.aligned.m16n8k16.row.col.f32.bf16.bf16.f32 "
                 "{%0,%1,%2,%3},{%4,%5,%6,%7},{%8,%9},{%0,%1,%2,%3};"
                 : "+f"(c[0]), "+f"(c[1]), "+f"(c[2]), "+f"(c[3])
                 : "r"(a[0]), "r"(a[1]), "r"(a[2]), "r"(a[3]), "r"(b[0]), "r"(b[1]));
}
__device__ __forceinline__ void mma_fp(float (&c)[4], const uint32_t (&a)[4], const uint32_t (&b)[2]) {
    asm volatile("mma.sync.aligned.m16n8k16.row.col.f32.f16.f16.f32 "
                 "{%0,%1,%2,%3},{%4,%5,%6,%7},{%8,%9},{%0,%1,%2,%3};"
                 : "+f"(c[0]), "+f"(c[1]), "+f"(c[2]), "+f"(c[3])
                 : "r"(a[0]), "r"(a[1]), "r"(a[2]), "r"(a[3]), "r"(b[0]), "r"(b[1]));
}

// ---------------- combined x prep: fp32 -> fp16 AND bf16 hi/lo in one read ----------------
__global__ void xprep_kernel(const float* __restrict__ in, __half* __restrict__ o16,
                             bf16* __restrict__ hi, bf16* __restrict__ lo, int n) {
    int i = blockIdx.x * blockDim.x + threadIdx.x;
    int stride = gridDim.x * blockDim.x;
    for (; i < n; i += stride) {
        float v = in[i];
        o16[i] = __float2half(v);
        bf16 h = __float2bfloat16(v);
        hi[i] = h;
        lo[i] = __float2bfloat16(v - __bfloat162float(h));
    }
}

// ---------------- fused 3-weight fp32 -> fp16 convert ----------------
__global__ void wcvt_kernel(const float* __restrict__ a, __half* __restrict__ oa,
                            const float* __restrict__ b, __half* __restrict__ ob,
                            const float* __restrict__ c, __half* __restrict__ oc, int n) {
    int i = blockIdx.x * blockDim.x + threadIdx.x;
    int stride = gridDim.x * blockDim.x;
    for (; i < 3 * n; i += stride) {
        if (i < n)            oa[i]         = __float2half(a[i]);
        else if (i < 2 * n)   ob[i - n]     = __float2half(b[i - n]);
        else                  oc[i - 2 * n] = __float2half(c[i - 2 * n]);
    }
}

// ---------------- W_q bf16 hi/lo split ----------------
__global__ void splitwq_kernel(const float* __restrict__ b, bf16* __restrict__ bh,
                               bf16* __restrict__ bl, int n) {
    int i = blockIdx.x * blockDim.x + threadIdx.x;
    int stride = gridDim.x * blockDim.x;
    for (; i < n; i += stride) {
        float v = b[i];
        bf16 h = __float2bfloat16(v);
        bh[i] = h;
        bl[i] = __float2bfloat16(v - __bfloat162float(h));
    }
}

// ============================================================================
// Single-pass fp16 GEMM: C = A*B. A row-major [M,K], B row-major [K,N].
// CTA tile 256x128x32, 256 threads, warp grid 4(m)x2(n), warp tile 64x64,
// 3-stage cp.async pipeline.
// mode 0: Cout(fp32)=acc          mode 1: Hout(fp16)=silu(Gin)*acc
// mode 2: Hout(fp16)=acc          mode 3: Cout(fp32)=acc+Es
// ============================================================================
#define HASTG   20480u
#define HSTAGEB 29184u

__global__ void __launch_bounds__(256, 1)
gemmh_kernel(const __half* __restrict__ A, const __half* __restrict__ B,
             int M, int N, int K,
             float* __restrict__ Cout, const __half* __restrict__ Gin,
             __half* __restrict__ Hout, const float* __restrict__ Es, int mode)
{
    extern __shared__ __align__(16) unsigned char smem_raw[];
    const uint32_t sb = (uint32_t)__cvta_generic_to_shared(smem_raw);

    const int tid  = threadIdx.x;
    const int lane = tid & 31;
    const int warp = tid >> 5;
    const int wm   = warp >> 1;   // 0..3
    const int wn   = warp & 1;    // 0..1
    const int mBlk = blockIdx.y * 256;
    const int nBlk = blockIdx.x * 128;
    const int KT   = K >> 5;

    float c[4][8][4];
#pragma unroll
    for (int i = 0; i < 4; i++)
#pragma unroll
        for (int j = 0; j < 8; j++)
#pragma unroll
            for (int k = 0; k < 4; k++) c[i][j][k] = 0.f;

    auto load_stage = [&](int st, int kt) {
        const int k0 = kt << 5;
        const uint32_t base = sb + (uint32_t)st * HSTAGEB;
#pragma unroll
        for (int r = 0; r < 4; ++r) {                  // A: 1024 chunks (256 rows x 4 segs)
            int id = tid + r * 256;
            int row = id >> 2, seg = id & 3;
            size_t go = (size_t)(mBlk + row) * K + k0 + seg * 8;
            cp16(base + (uint32_t)row * 80u + (uint32_t)seg * 16u, A + go);
        }
#pragma unroll
        for (int r = 0; r < 2; ++r) {                  // B: 512 chunks (32 rows x 16 segs)
            int id = tid + r * 256;
            int row = id >> 4, seg = id & 15;
            size_t go = (size_t)(k0 + row) * N + nBlk + seg * 8;
            cp16(base + HASTG + (uint32_t)row * 272u + (uint32_t)seg * 16u, B + go);
        }
    };

    load_stage(0, 0); CP_COMMIT();
    load_stage(1, 1); CP_COMMIT();

    int st = 0;
    for (int kt = 0; kt < KT; ++kt) {
        if (kt + 2 < KT) CP_WAIT1(); else CP_WAIT0();
        __syncthreads();
        if (kt + 2 < KT) {
            int st2 = st + 2; if (st2 >= 3) st2 -= 3;
            load_stage(st2, kt + 2);
            CP_COMMIT();
        }
        const uint32_t base = sb + (uint32_t)st * HSTAGEB;
#pragma unroll
        for (int kk = 0; kk < 2; ++kk) {
            const uint32_t acol = (uint32_t)(kk * 16 + (lane >> 4) * 8) * 2u;
            const uint32_t brow = base + HASTG + (uint32_t)(kk * 16 + (lane & 15)) * 272u;

            uint32_t a[4][4], b[8][2];
#pragma unroll
            for (int mi = 0; mi < 4; mi++)
                ldsm_x4(a[mi], base + (uint32_t)(wm * 64 + mi * 16 + (lane & 15)) * 80u + acol);
#pragma unroll
            for (int nj = 0; nj < 4; nj++) {
                uint32_t r[4];
                ldsm_x4t(r, brow + (uint32_t)(wn * 64 + nj * 16 + (lane >> 4) * 8) * 2u);
                b[2*nj][0] = r[0]; b[2*nj][1] = r[1];
                b[2*nj+1][0] = r[2]; b[2*nj+1][1] = r[3];
            }
#pragma unroll
            for (int mi = 0; mi < 4; mi++)
#pragma unroll
                for (int nt = 0; nt < 8; nt++) mma_fp(c[mi][nt], a[mi], b[nt]);
        }
        ++st; if (st >= 3) st = 0;
    }

    // epilogue
#pragma unroll
    for (int mi = 0; mi < 4; mi++) {
#pragma unroll
        for (int nt = 0; nt < 8; nt++) {
            int row = mBlk + wm * 64 + mi * 16 + (lane >> 2);
            int col = nBlk + wn * 64 + nt * 8 + (lane & 3) * 2;
#pragma unroll
            for (int hrow = 0; hrow < 2; ++hrow) {
                int r = row + hrow * 8;
                size_t i0 = (size_t)r * N + col;
                float v0 = c[mi][nt][hrow * 2 + 0];
                float v1 = c[mi][nt][hrow * 2 + 1];
                if (mode == 0) {
                    Cout[i0]     = v0;
                    Cout[i0 + 1] = v1;
                } else if (mode == 1) {
                    float gg0 = __half2float(Gin[i0]), gg1 = __half2float(Gin[i0 + 1]);
                    float hv0 = gg0 / (1.f + expf(-gg0)) * v0;
                    float hv1 = gg1 / (1.f + expf(-gg1)) * v1;
                    Hout[i0]     = __float2half(hv0);
                    Hout[i0 + 1] = __float2half(hv1);
                } else if (mode == 2) {
                    Hout[i0]     = __float2half(v0);
                    Hout[i0 + 1] = __float2half(v1);
                } else {
                    Cout[i0]     = v0 + Es[i0];
                    Cout[i0 + 1] = v1 + Es[i0 + 1];
                }
            }
        }
    }
}

// ============================================================================
// bf16x3 GEMM for the Q projection (protects top-k routing). Proven structure.
// ============================================================================
#define ASTG   20480u
#define BSTG   8704u
#define STAGEB 58368u

__global__ void __launch_bounds__(256, 1)
gemm3x_kernel(const bf16* __restrict__ Ah, const bf16* __restrict__ Al,
              const bf16* __restrict__ Bh, const bf16* __restrict__ Bl,
              int M, int N, int K, float* __restrict__ Cout)
{
    extern __shared__ __align__(16) unsigned char smem_raw[];
    const uint32_t sb = (uint32_t)__cvta_generic_to_shared(smem_raw);

    const int tid  = threadIdx.x;
    const int lane = tid & 31;
    const int warp = tid >> 5;
    const int wm   = warp >> 1;
    const int wn   = warp & 1;
    const int mBlk = blockIdx.y * 256;
    const int nBlk = blockIdx.x * 128;
    const int KT   = K >> 5;

    float c[4][8][4];
#pragma unroll
    for (int i = 0; i < 4; i++)
#pragma unroll
        for (int j = 0; j < 8; j++)
#pragma unroll
            for (int k = 0; k < 4; k++) c[i][j][k] = 0.f;

    auto load_stage = [&](int st, int kt) {
        const int k0 = kt << 5;
        const uint32_t base = sb + (uint32_t)st * STAGEB;
#pragma unroll
        for (int r = 0; r < 4; ++r) {
            int id = tid + r * 256;
            int row = id >> 2, seg = id & 3;
            size_t go = (size_t)(mBlk + row) * K + k0 + seg * 8;
            uint32_t so = base + (uint32_t)row * 80u + (uint32_t)seg * 16u;
            cp16(so, Ah + go);
            cp16(so + ASTG, Al + go);
        }
#pragma unroll
        for (int r = 0; r < 2; ++r) {
            int id = tid + r * 256;
            int row = id >> 4, seg = id & 15;
            size_t go = (size_t)(k0 + row) * N + nBlk + seg * 8;
            uint32_t so = base + 2 * ASTG + (uint32_t)row * 272u + (uint32_t)seg * 16u;
            cp16(so, Bh + go);
            cp16(so + BSTG, Bl + go);
        }
    };

    load_stage(0, 0); CP_COMMIT();
    load_stage(1, 1); CP_COMMIT();

    int st = 0;
    for (int kt = 0; kt < KT; ++kt) {
        if (kt + 2 < KT) CP_WAIT1(); else CP_WAIT0();
        __syncthreads();
        if (kt + 2 < KT) {
            int st2 = st + 2; if (st2 >= 3) st2 -= 3;
            load_stage(st2, kt + 2);
            CP_COMMIT();
        }
        const uint32_t base = sb + (uint32_t)st * STAGEB;
#pragma unroll
        for (int kk = 0; kk < 2; ++kk) {
            const uint32_t acol = (uint32_t)(kk * 16 + (lane >> 4) * 8) * 2u;
            const uint32_t brow = base + 2 * ASTG + (uint32_t)(kk * 16 + (lane & 15)) * 272u;

            uint32_t ah[4][4], bh[8][2];
#pragma unroll
            for (int mi = 0; mi < 4; mi++)
                ldsm_x4(ah[mi], base + (uint32_t)(wm * 64 + mi * 16 + (lane & 15)) * 80u + acol);
#pragma unroll
            for (int nj = 0; nj < 4; nj++) {
                uint32_t r[4];
                ldsm_x4t(r, brow + (uint32_t)(wn * 64 + nj * 16 + (lane >> 4) * 8) * 2u);
                bh[2*nj][0] = r[0]; bh[2*nj][1] = r[1];
                bh[2*nj+1][0] = r[2]; bh[2*nj+1][1] = r[3];
            }
#pragma unroll
            for (int mi = 0; mi < 4; mi++)
#pragma unroll
                for (int nt = 0; nt < 8; nt++) mma_bf(c[mi][nt], ah[mi], bh[nt]);

            uint32_t al[4][4];
#pragma unroll
            for (int mi = 0; mi < 4; mi++)
                ldsm_x4(al[mi], base + ASTG + (uint32_t)(wm * 64 + mi * 16 + (lane & 15)) * 80u + acol);
#pragma unroll
            for (int mi = 0; mi < 4; mi++)
#pragma unroll
                for (int nt = 0; nt < 8; nt++) mma_bf(c[mi][nt], al[mi], bh[nt]);

            uint32_t bl[8][2];
#pragma unroll
            for (int nj = 0; nj < 4; nj++) {
                uint32_t r[4];
                ldsm_x4t(r, brow + BSTG + (uint32_t)(wn * 64 + nj * 16 + (lane >> 4) * 8) * 2u);
                bl[2*nj][0] = r[0]; bl[2*nj][1] = r[1];
                bl[2*nj+1][0] = r[2]; bl[2*nj+1][1] = r[3];
            }
#pragma unroll
            for (int mi = 0; mi < 4; mi++)
#pragma unroll
                for (int nt = 0; nt < 8; nt++) mma_bf(c[mi][nt], ah[mi], bl[nt]);
        }
        ++st; if (st >= 3) st = 0;
    }

#pragma unroll
    for (int mi = 0; mi < 4; mi++)
#pragma unroll
        for (int nt = 0; nt < 8; nt++) {
            int row = mBlk + wm * 64 + mi * 16 + (lane >> 2);
            int col = nBlk + wn * 64 + nt * 8 + (lane & 3) * 2;
#pragma unroll
            for (int hrow = 0; hrow < 2; ++hrow) {
                int r = row + hrow * 8;
                size_t i0 = (size_t)r * N + col;
                Cout[i0]     = c[mi][nt][hrow * 2 + 0];
                Cout[i0 + 1] = c[mi][nt][hrow * 2 + 1];
            }
        }
}

// ---------------- product-key routing: top8 x top8 -> top8, softmax ----------------
__global__ void __launch_bounds__(256)
routing_kernel(const float* __restrict__ Q, const float* __restrict__ keys,
               int* __restrict__ eidx, float* __restrict__ probs)
{
    const int warp = threadIdx.x >> 5, lane = threadIdx.x & 31;
    const int m = blockIdx.x * 8 + warp;

    __shared__ float s_q[8][128];
    __shared__ float s_tsx[8][8], s_tsy[8][8];
    __shared__ int   s_tix[8][8], s_tiy[8][8];
    __shared__ float s_sel[8][8];
    __shared__ int   s_pos[8][8];

    const int j0 = (m >> 1);
    const int j1 = 4096 + (m >> 1);
    const int o  = (m & 1) * 64;
    s_q[warp][lane]           = Q[j0 * RET + o + lane];
    s_q[warp][lane + 32]      = Q[j0 * RET + o + lane + 32];
    s_q[warp][64 + lane]      = Q[j1 * RET + o + lane];
    s_q[warp][64 + lane + 32] = Q[j1 * RET + o + lane + 32];
    __syncwarp();

    float rx0 = 0.f, rx1 = 0.f, ry0 = 0.f, ry1 = 0.f;
#pragma unroll 8
    for (int d = 0; d < 64; ++d) {
        float qx = s_q[warp][d], qy = s_q[warp][64 + d];
        rx0 += qx * keys[d * 64 + lane];
        rx1 += qx * keys[d * 64 + lane + 32];
        ry0 += qy * keys[4096 + d * 64 + lane];
        ry1 += qy * keys[4096 + d * 64 + lane + 32];
    }

#pragma unroll 1
    for (int r = 0; r < 8; ++r) {
        float v; int i;
        if (rx0 >= rx1) { v = rx0; i = lane; } else { v = rx1; i = lane + 32; }
#pragma unroll
        for (int s = 16; s; s >>= 1) {
            float ov = __shfl_xor_sync(0xffffffffu, v, s);
            int   oi = __shfl_xor_sync(0xffffffffu, i, s);
            if (ov > v || (ov == v && oi < i)) { v = ov; i = oi; }
        }
        if (lane == 0) { s_tsx[warp][r] = v; s_tix[warp][r] = i; }
        if (i == lane)      rx0 = -INFINITY;
        if (i == lane + 32) rx1 = -INFINITY;
    }
#pragma unroll 1
    for (int r = 0; r < 8; ++r) {
        float v; int i;
        if (ry0 >= ry1) { v = ry0; i = lane; } else { v = ry1; i = lane + 32; }
#pragma unroll
        for (int s = 16; s; s >>= 1) {
            float ov = __shfl_xor_sync(0xffffffffu, v, s);
            int   oi = __shfl_xor_sync(0xffffffffu, i, s);
            if (ov > v || (ov == v && oi < i)) { v = ov; i = oi; }
        }
        if (lane == 0) { s_tsy[warp][r] = v; s_tiy[warp][r] = i; }
        if (i == lane)      ry0 = -INFINITY;
        if (i == lane + 32) ry1 = -INFINITY;
    }
    __syncwarp();

    float c0 = s_tsx[warp][lane >> 3]        + s_tsy[warp][lane & 7];
    float c1 = s_tsx[warp][(lane + 32) >> 3] + s_tsy[warp][(lane + 32) & 7];
#pragma unroll 1
    for (int r = 0; r < 8; ++r) {
        float v; int p;
        if (c0 >= c1) { v = c0; p = lane; } else { v = c1; p = lane + 32; }
#pragma unroll
        for (int s = 16; s; s >>= 1) {
            float ov = __shfl_xor_sync(0xffffffffu, v, s);
            int   op = __shfl_xor_sync(0xffffffffu, p, s);
            if (ov > v || (ov == v && op < p)) { v = ov; p = op; }
        }
        if (lane == 0) { s_sel[warp][r] = v; s_pos[warp][r] = p; }
        if (p == lane)      c0 = -INFINITY;
        if (p == lane + 32) c1 = -INFINITY;
    }
    __syncwarp();

    if (lane < 8) {
        float mx = s_sel[warp][0];
        float e  = expf(s_sel[warp][lane] - mx);
        float sum = e;
#pragma unroll
        for (int s = 4; s; s >>= 1) sum += __shfl_xor_sync(0xffu, sum, s);
        int p  = s_pos[warp][lane];
        int ex = s_tix[warp][p >> 3] * 64 + s_tiy[warp][p & 7];
        eidx[m * TOPK + lane]  = ex;
        probs[m * TOPK + lane] = e / sum;
    }
}

// ---------------- per-token expert compute (writes g_es, no out RMW) ----------------
__global__ void __launch_bounds__(256)
expert_kernel(const float* __restrict__ x, const float* __restrict__ down_embed,
              const float* __restrict__ up_embed, const int* __restrict__ eidx,
              const float* __restrict__ probs, float* __restrict__ es)
{
    const int n = blockIdx.x;
    __shared__ __align__(16) float sx[HID];
    __shared__ float coeff[TOPK];
    __shared__ int   se[TOPK];

    const int tid = threadIdx.x;
    const float4* xin = (const float4*)(x + (size_t)n * HID);
    float4* sx4 = (float4*)sx;
    sx4[tid]       = xin[tid];
    sx4[tid + 256] = xin[tid + 256];
    if (tid < TOPK) se[tid] = eidx[n * TOPK + tid];
    __syncthreads();

    const int w = tid >> 5, lane = tid & 31;
    {
        const float* de = down_embed + (size_t)se[w] * HID;
        float acc = 0.f;
#pragma unroll
        for (int i = 0; i < 64; ++i) acc += sx[i * 32 + lane] * de[i * 32 + lane];
#pragma unroll
        for (int s = 16; s; s >>= 1) acc += __shfl_xor_sync(0xffffffffu, acc, s);
        if (lane == 0)
            coeff[w] = acc / (1.f + expf(-acc)) * probs[n * TOPK + w];
    }
    __syncthreads();

    float cc[TOPK]; int ee[TOPK];
#pragma unroll
    for (int k = 0; k < TOPK; ++k) { cc[k] = coeff[k]; ee[k] = se[k]; }

#pragma unroll
    for (int h = tid; h < HID; h += 256) {
        float acc = 0.f;
#pragma unroll
        for (int k = 0; k < TOPK; ++k)
            acc += cc[k] * up_embed[(size_t)ee[k] * HID + h];
        es[(size_t)n * HID + h] = acc;
    }
}

// ---------------- launch ----------------
extern "C" void kernel_launch(void* const* d_in, const int* in_sizes, int n_in,
                              void* d_out, int out_size) {
    (void)in_sizes; (void)n_in; (void)out_size;
    const float* x    = (const float*)d_in[0];
    const float* Wq   = (const float*)d_in[1];
    const float* keys = (const float*)d_in[2];
    const float* de   = (const float*)d_in[3];
    const float* ue   = (const float*)d_in[4];
    const float* gw   = (const float*)d_in[5];
    const float* uw   = (const float*)d_in[6];
    const float* dw   = (const float*)d_in[7];
    float* out = (float*)d_out;

    void *x16, *gw16, *uw16, *dw16, *G16, *h16, *esp;
    void *xh, *xl, *wqh, *wql, *Qp, *idxp, *pp;
    cudaGetSymbolAddress(&x16,  g_x16);   cudaGetSymbolAddress(&gw16, g_gw16);
    cudaGetSymbolAddress(&uw16, g_uw16);  cudaGetSymbolAddress(&dw16, g_dw16);
    cudaGetSymbolAddress(&G16,  g_G16);   cudaGetSymbolAddress(&h16,  g_h16);
    cudaGetSymbolAddress(&esp,  g_es);
    cudaGetSymbolAddress(&xh,   g_x_hi);  cudaGetSymbolAddress(&xl,   g_x_lo);
    cudaGetSymbolAddress(&wqh,  g_wq_hi); cudaGetSymbolAddress(&wql,  g_wq_lo);
    cudaGetSymbolAddress(&Qp,   g_Q);
    cudaGetSymbolAddress(&idxp, g_eidx);  cudaGetSymbolAddress(&pp,   g_prob);

    const int SMEM_H  = 3 * 29184;   // 87552
    const int SMEM_3X = 3 * 58368;   // 175104
    cudaFuncSetAttribute(gemmh_kernel,  cudaFuncAttributeMaxDynamicSharedMemorySize, SMEM_H);
    cudaFuncSetAttribute(gemm3x_kernel, cudaFuncAttributeMaxDynamicSharedMemorySize, SMEM_3X);

    // side stream + fork/join events: created once, on the (uncaptured)
    // correctness call; reused identically on the capture call.
    static cudaStream_t s_side = nullptr;
    static cudaEvent_t  ev_fork = nullptr, ev_join = nullptr;
    if (s_side == nullptr) {
        cudaStreamCreateWithFlags(&s_side, cudaStreamNonBlocking);
        cudaEventCreateWithFlags(&ev_fork, cudaEventDisableTiming);
        cudaEventCreateWithFlags(&ev_join, cudaEventDisableTiming);
    }

    // ---- prep (main stream) ----
    xprep_kernel<<<2048, 256>>>(x, (__half*)x16, (bf16*)xh, (bf16*)xl, NTOK * HID);
    wcvt_kernel<<<4096, 256>>>(gw, (__half*)gw16, uw, (__half*)uw16, dw, (__half*)dw16, HID * INTER);
    splitwq_kernel<<<256, 256>>>(Wq, (bf16*)wqh, (bf16*)wql, HID * RET);

    // ---- fork: side stream runs the routing/expert branch ----
    cudaEventRecord(ev_fork, 0);
    cudaStreamWaitEvent(s_side, ev_fork, 0);

    gemm3x_kernel<<<dim3(1, NTOK / 256), 256, SMEM_3X, s_side>>>(
        (const bf16*)xh, (const bf16*)xl, (const bf16*)wqh, (const bf16*)wql,
        NTOK, RET, HID, (float*)Qp);
    routing_kernel<<<NTOK / 8, 256, 0, s_side>>>((const float*)Qp, keys, (int*)idxp, (float*)pp);
    expert_kernel<<<NTOK, 256, 0, s_side>>>(x, de, ue, (const int*)idxp, (const float*)pp, (float*)esp);
    cudaEventRecord(ev_join, s_side);

    // ---- main stream: gate -> up (overlapped with side branch) ----
    gemmh_kernel<<<dim3(INTER / 128, NTOK / 256), 256, SMEM_H>>>(
        (const __half*)x16, (const __half*)gw16, NTOK, INTER, HID,
        nullptr, nullptr, (__half*)G16, nullptr, 2);
    gemmh_kernel<<<dim3(INTER / 128, NTOK / 256), 256, SMEM_H>>>(
        (const __half*)x16, (const __half*)uw16, NTOK, INTER, HID,
        nullptr, (const __half*)G16, (__half*)h16, nullptr, 1);

    // ---- join, then down GEMM with fused expert add ----
    cudaStreamWaitEvent(0, ev_join, 0);
    gemmh_kernel<<<dim3(HID / 128, NTOK / 256), 256, SMEM_H>>>(
        (const __half*)h16, (const __half*)dw16, NTOK, HID, INTER,
        out, nullptr, nullptr, (const float*)esp, 3);
}

// round 11
// speedup vs baseline: 2.6284x; 1.2006x over previous
#include <cuda_runtime.h>
#include <cuda_bf16.h>
#include <cuda_fp16.h>
#include <math.h>
#include <stdint.h>

using bf16 = __nv_bfloat16;

// ---------------- problem constants ----------------
#define NTOK  8192     // B*S
#define HID   2048
#define INTER 8192
#define RET   128
#define TOPK  8

// ---------------- scratch (__device__ globals; no allocation allowed) ----------------
__device__ __align__(256) __half g_x16[(size_t)NTOK * HID];
__device__ __align__(256) __half g_gw16[(size_t)HID * INTER];
__device__ __align__(256) __half g_uw16[(size_t)HID * INTER];
__device__ __align__(256) __half g_dw16[(size_t)INTER * HID];
__device__ __align__(256) __half g_G16[(size_t)NTOK * INTER];    // gate pre-act (fp16)
__device__ __align__(256) __half g_h16[(size_t)NTOK * INTER];    // silu(g)*u (fp16)
__device__ __align__(256) bf16  g_x_hi[(size_t)NTOK * HID];      // Q path (bf16x3)
__device__ __align__(256) bf16  g_x_lo[(size_t)NTOK * HID];
__device__ __align__(256) bf16  g_wq_hi[HID * RET];
__device__ __align__(256) bf16  g_wq_lo[HID * RET];
__device__ __align__(256) float g_Q[NTOK * RET];
__device__ __align__(256) int   g_eidx[NTOK * TOPK];
__device__ __align__(256) float g_prob[NTOK * TOPK];
__device__ __align__(256) float g_es[(size_t)NTOK * HID];        // expert states

// ---------------- helpers ----------------
__device__ __forceinline__ void cp16(uint32_t s, const void* g) {
    asm volatile("cp.async.cg.shared.global [%0], [%1], 16;\n" :: "r"(s), "l"(g));
}
#define CP_COMMIT() asm volatile("cp.async.commit_group;\n" ::: "memory")
#define CP_WAIT1()  asm volatile("cp.async.wait_group 1;\n" ::: "memory")
#define CP_WAIT0()  asm volatile("cp.async.wait_group 0;\n" ::: "memory")

__device__ __forceinline__ void ldsm_x4(uint32_t (&r)[4], uint32_t addr) {
    asm volatile("ldmatrix.sync.aligned.m8n8.x4.shared.b16 {%0,%1,%2,%3}, [%4];"
                 : "=r"(r[0]), "=r"(r[1]), "=r"(r[2]), "=r"(r[3]) : "r"(addr));
}
__device__ __forceinline__ void ldsm_x4t(uint32_t (&r)[4], uint32_t addr) {
    asm volatile("ldmatrix.sync.aligned.m8n8.x4.trans.shared.b16 {%0,%1,%2,%3}, [%4];"
                 : "=r"(r[0]), "=r"(r[1]), "=r"(r[2]), "=r"(r[3]) : "r"(addr));
}
__device__ __forceinline__ void mma_bf(float (&c)[4], const uint32_t (&a)[4], const uint32_t (&b)[2]) {
    asm volatile("mma.sync.aligned.m16n8k16.row.col.f32.bf16.bf16.f32 "
                 "{%0,%1,%2,%3},{%4,%5,%6,%7},{%8,%9},{%0,%1,%2,%3};"
                 : "+f"(c[0]), "+f"(c[1]), "+f"(c[2]), "+f"(c[3])
                 : "r"(a[0]), "r"(a[1]), "r"(a[2]), "r"(a[3]), "r"(b[0]), "r"(b[1]));
}
__device__ __forceinline__ void mma_fp(float (&c)[4], const uint32_t (&a)[4], const uint32_t (&b)[2]) {
    asm volatile("mma.sync.aligned.m16n8k16.row.col.f32.f16.f16.f32 "
                 "{%0,%1,%2,%3},{%4,%5,%6,%7},{%8,%9},{%0,%1,%2,%3};"
                 : "+f"(c[0]), "+f"(c[1]), "+f"(c[2]), "+f"(c[3])
                 : "r"(a[0]), "r"(a[1]), "r"(a[2]), "r"(a[3]), "r"(b[0]), "r"(b[1]));
}

// ---------------- combined x prep: fp32 -> fp16 AND bf16 hi/lo in one read ----------------
__global__ void xprep_kernel(const float* __restrict__ in, __half* __restrict__ o16,
                             bf16* __restrict__ hi, bf16* __restrict__ lo, int n) {
    int i = blockIdx.x * blockDim.x + threadIdx.x;
    int stride = gridDim.x * blockDim.x;
    for (; i < n; i += stride) {
        float v = in[i];
        o16[i] = __float2half(v);
        bf16 h = __float2bfloat16(v);
        hi[i] = h;
        lo[i] = __float2bfloat16(v - __bfloat162float(h));
    }
}

// ---------------- fused 3-weight fp32 -> fp16 convert ----------------
__global__ void wcvt_kernel(const float* __restrict__ a, __half* __restrict__ oa,
                            const float* __restrict__ b, __half* __restrict__ ob,
                            const float* __restrict__ c, __half* __restrict__ oc, int n) {
    int i = blockIdx.x * blockDim.x + threadIdx.x;
    int stride = gridDim.x * blockDim.x;
    for (; i < 3 * n; i += stride) {
        if (i < n)            oa[i]         = __float2half(a[i]);
        else if (i < 2 * n)   ob[i - n]     = __float2half(b[i - n]);
        else                  oc[i - 2 * n] = __float2half(c[i - 2 * n]);
    }
}

// ---------------- W_q bf16 hi/lo split ----------------
__global__ void splitwq_kernel(const float* __restrict__ b, bf16* __restrict__ bh,
                               bf16* __restrict__ bl, int n) {
    int i = blockIdx.x * blockDim.x + threadIdx.x;
    int stride = gridDim.x * blockDim.x;
    for (; i < n; i += stride) {
        float v = b[i];
        bf16 h = __float2bfloat16(v);
        bh[i] = h;
        bl[i] = __float2bfloat16(v - __bfloat162float(h));
    }
}

// ============================================================================
// Single-pass fp16 GEMM with register-fragment double buffering.
// C = A*B. A row-major [M,K], B row-major [K,N]. CTA tile 256x128x32,
// 256 threads, warp grid 4(m)x2(n), warp tile 64x64, 3-stage cp.async pipeline.
// mode 0: Cout(fp32)=acc          mode 1: Hout(fp16)=silu(Gin)*acc
// mode 2: Hout(fp16)=acc          mode 3: Cout(fp32)=acc+Es
// ============================================================================
#define HASTG   20480u
#define HSTAGEB 29184u

__global__ void __launch_bounds__(256, 1)
gemmh_kernel(const __half* __restrict__ A, const __half* __restrict__ B,
             int M, int N, int K,
             float* __restrict__ Cout, const __half* __restrict__ Gin,
             __half* __restrict__ Hout, const float* __restrict__ Es, int mode)
{
    extern __shared__ __align__(16) unsigned char smem_raw[];
    const uint32_t sb = (uint32_t)__cvta_generic_to_shared(smem_raw);

    const int tid  = threadIdx.x;
    const int lane = tid & 31;
    const int warp = tid >> 5;
    const int wm   = warp >> 1;   // 0..3
    const int wn   = warp & 1;    // 0..1
    const int mBlk = blockIdx.y * 256;
    const int nBlk = blockIdx.x * 128;
    const int KT   = K >> 5;

    float c[4][8][4];
#pragma unroll
    for (int i = 0; i < 4; i++)
#pragma unroll
        for (int j = 0; j < 8; j++)
#pragma unroll
            for (int k = 0; k < 4; k++) c[i][j][k] = 0.f;

    uint32_t fa[2][4][4], fb[2][8][2];

    auto load_stage = [&](int st, int kt) {
        const int k0 = kt << 5;
        const uint32_t base = sb + (uint32_t)st * HSTAGEB;
#pragma unroll
        for (int r = 0; r < 4; ++r) {                  // A: 1024 chunks (256 rows x 4 segs)
            int id = tid + r * 256;
            int row = id >> 2, seg = id & 3;
            size_t go = (size_t)(mBlk + row) * K + k0 + seg * 8;
            cp16(base + (uint32_t)row * 80u + (uint32_t)seg * 16u, A + go);
        }
#pragma unroll
        for (int r = 0; r < 2; ++r) {                  // B: 512 chunks (32 rows x 16 segs)
            int id = tid + r * 256;
            int row = id >> 4, seg = id & 15;
            size_t go = (size_t)(k0 + row) * N + nBlk + seg * 8;
            cp16(base + HASTG + (uint32_t)row * 272u + (uint32_t)seg * 16u, B + go);
        }
    };

    auto ldfrags = [&](int buf, uint32_t base, int kk) {
        const uint32_t acol = (uint32_t)(kk * 16 + (lane >> 4) * 8) * 2u;
        const uint32_t brow = base + HASTG + (uint32_t)(kk * 16 + (lane & 15)) * 272u;
#pragma unroll
        for (int mi = 0; mi < 4; mi++)
            ldsm_x4(fa[buf][mi], base + (uint32_t)(wm * 64 + mi * 16 + (lane & 15)) * 80u + acol);
#pragma unroll
        for (int nj = 0; nj < 4; nj++) {
            uint32_t r[4];
            ldsm_x4t(r, brow + (uint32_t)(wn * 64 + nj * 16 + (lane >> 4) * 8) * 2u);
            fb[buf][2*nj][0]   = r[0]; fb[buf][2*nj][1]   = r[1];
            fb[buf][2*nj+1][0] = r[2]; fb[buf][2*nj+1][1] = r[3];
        }
    };

    load_stage(0, 0); CP_COMMIT();
    load_stage(1, 1); CP_COMMIT();
    CP_WAIT1();
    __syncthreads();
    ldfrags(0, sb, 0);                                  // (kt=0, kk=0)

    int st = 0;
    for (int kt = 0; kt < KT; ++kt) {
        const uint32_t base = sb + (uint32_t)st * HSTAGEB;

        // prefetch kk=1 fragments; overlapped by kk=0 MMAs below
        ldfrags(1, base, 1);
#pragma unroll
        for (int mi = 0; mi < 4; mi++)
#pragma unroll
            for (int nt = 0; nt < 8; nt++) mma_fp(c[mi][nt], fa[0][mi], fb[0][nt]);

        // stage (kt+2)%3 == stage (kt-1)%3: all warps finished reading it
        // before the sync of iteration kt-1 -> safe to overwrite.
        if (kt + 2 < KT) { load_stage((kt + 2) % 3, kt + 2); CP_COMMIT(); }

        if (kt + 1 < KT) {
            if (kt + 2 < KT) CP_WAIT1(); else CP_WAIT0();
            __syncthreads();
            const int stn = (st + 1 >= 3) ? 0 : st + 1;
            // prefetch next k-tile's kk=0 fragments; overlapped by kk=1 MMAs
            ldfrags(0, sb + (uint32_t)stn * HSTAGEB, 0);
        }
#pragma unroll
        for (int mi = 0; mi < 4; mi++)
#pragma unroll
            for (int nt = 0; nt < 8; nt++) mma_fp(c[mi][nt], fa[1][mi], fb[1][nt]);

        ++st; if (st >= 3) st = 0;
    }

    // epilogue
#pragma unroll
    for (int mi = 0; mi < 4; mi++) {
#pragma unroll
        for (int nt = 0; nt < 8; nt++) {
            int row = mBlk + wm * 64 + mi * 16 + (lane >> 2);
            int col = nBlk + wn * 64 + nt * 8 + (lane & 3) * 2;
#pragma unroll
            for (int hrow = 0; hrow < 2; ++hrow) {
                int r = row + hrow * 8;
                size_t i0 = (size_t)r * N + col;
                float v0 = c[mi][nt][hrow * 2 + 0];
                float v1 = c[mi][nt][hrow * 2 + 1];
                if (mode == 0) {
                    Cout[i0]     = v0;
                    Cout[i0 + 1] = v1;
                } else if (mode == 1) {
                    float gg0 = __half2float(Gin[i0]), gg1 = __half2float(Gin[i0 + 1]);
                    float hv0 = gg0 / (1.f + expf(-gg0)) * v0;
                    float hv1 = gg1 / (1.f + expf(-gg1)) * v1;
                    Hout[i0]     = __float2half(hv0);
                    Hout[i0 + 1] = __float2half(hv1);
                } else if (mode == 2) {
                    Hout[i0]     = __float2half(v0);
                    Hout[i0 + 1] = __float2half(v1);
                } else {
                    Cout[i0]     = v0 + Es[i0];
                    Cout[i0 + 1] = v1 + Es[i0 + 1];
                }
            }
        }
    }
}

// ============================================================================
// bf16x3 GEMM for the Q projection (protects top-k routing). Proven structure.
// ============================================================================
#define ASTG   20480u
#define BSTG   8704u
#define STAGEB 58368u

__global__ void __launch_bounds__(256, 1)
gemm3x_kernel(const bf16* __restrict__ Ah, const bf16* __restrict__ Al,
              const bf16* __restrict__ Bh, const bf16* __restrict__ Bl,
              int M, int N, int K, float* __restrict__ Cout)
{
    extern __shared__ __align__(16) unsigned char smem_raw[];
    const uint32_t sb = (uint32_t)__cvta_generic_to_shared(smem_raw);

    const int tid  = threadIdx.x;
    const int lane = tid & 31;
    const int warp = tid >> 5;
    const int wm   = warp >> 1;
    const int wn   = warp & 1;
    const int mBlk = blockIdx.y * 256;
    const int nBlk = blockIdx.x * 128;
    const int KT   = K >> 5;

    float c[4][8][4];
#pragma unroll
    for (int i = 0; i < 4; i++)
#pragma unroll
        for (int j = 0; j < 8; j++)
#pragma unroll
            for (int k = 0; k < 4; k++) c[i][j][k] = 0.f;

    auto load_stage = [&](int st, int kt) {
        const int k0 = kt << 5;
        const uint32_t base = sb + (uint32_t)st * STAGEB;
#pragma unroll
        for (int r = 0; r < 4; ++r) {
            int id = tid + r * 256;
            int row = id >> 2, seg = id & 3;
            size_t go = (size_t)(mBlk + row) * K + k0 + seg * 8;
            uint32_t so = base + (uint32_t)row * 80u + (uint32_t)seg * 16u;
            cp16(so, Ah + go);
            cp16(so + ASTG, Al + go);
        }
#pragma unroll
        for (int r = 0; r < 2; ++r) {
            int id = tid + r * 256;
            int row = id >> 4, seg = id & 15;
            size_t go = (size_t)(k0 + row) * N + nBlk + seg * 8;
            uint32_t so = base + 2 * ASTG + (uint32_t)row * 272u + (uint32_t)seg * 16u;
            cp16(so, Bh + go);
            cp16(so + BSTG, Bl + go);
        }
    };

    load_stage(0, 0); CP_COMMIT();
    load_stage(1, 1); CP_COMMIT();

    int st = 0;
    for (int kt = 0; kt < KT; ++kt) {
        if (kt + 2 < KT) CP_WAIT1(); else CP_WAIT0();
        __syncthreads();
        if (kt + 2 < KT) {
            int st2 = st + 2; if (st2 >= 3) st2 -= 3;
            load_stage(st2, kt + 2);
            CP_COMMIT();
        }
        const uint32_t base = sb + (uint32_t)st * STAGEB;
#pragma unroll
        for (int kk = 0; kk < 2; ++kk) {
            const uint32_t acol = (uint32_t)(kk * 16 + (lane >> 4) * 8) * 2u;
            const uint32_t brow = base + 2 * ASTG + (uint32_t)(kk * 16 + (lane & 15)) * 272u;

            uint32_t ah[4][4], bh[8][2];
#pragma unroll
            for (int mi = 0; mi < 4; mi++)
                ldsm_x4(ah[mi], base + (uint32_t)(wm * 64 + mi * 16 + (lane & 15)) * 80u + acol);
#pragma unroll
            for (int nj = 0; nj < 4; nj++) {
                uint32_t r[4];
                ldsm_x4t(r, brow + (uint32_t)(wn * 64 + nj * 16 + (lane >> 4) * 8) * 2u);
                bh[2*nj][0] = r[0]; bh[2*nj][1] = r[1];
                bh[2*nj+1][0] = r[2]; bh[2*nj+1][1] = r[3];
            }
#pragma unroll
            for (int mi = 0; mi < 4; mi++)
#pragma unroll
                for (int nt = 0; nt < 8; nt++) mma_bf(c[mi][nt], ah[mi], bh[nt]);

            uint32_t al[4][4];
#pragma unroll
            for (int mi = 0; mi < 4; mi++)
                ldsm_x4(al[mi], base + ASTG + (uint32_t)(wm * 64 + mi * 16 + (lane & 15)) * 80u + acol);
#pragma unroll
            for (int mi = 0; mi < 4; mi++)
#pragma unroll
                for (int nt = 0; nt < 8; nt++) mma_bf(c[mi][nt], al[mi], bh[nt]);

            uint32_t bl[8][2];
#pragma unroll
            for (int nj = 0; nj < 4; nj++) {
                uint32_t r[4];
                ldsm_x4t(r, brow + BSTG + (uint32_t)(wn * 64 + nj * 16 + (lane >> 4) * 8) * 2u);
                bl[2*nj][0] = r[0]; bl[2*nj][1] = r[1];
                bl[2*nj+1][0] = r[2]; bl[2*nj+1][1] = r[3];
            }
#pragma unroll
            for (int mi = 0; mi < 4; mi++)
#pragma unroll
                for (int nt = 0; nt < 8; nt++) mma_bf(c[mi][nt], ah[mi], bl[nt]);
        }
        ++st; if (st >= 3) st = 0;
    }

#pragma unroll
    for (int mi = 0; mi < 4; mi++)
#pragma unroll
        for (int nt = 0; nt < 8; nt++) {
            int row = mBlk + wm * 64 + mi * 16 + (lane >> 2);
            int col = nBlk + wn * 64 + nt * 8 + (lane & 3) * 2;
#pragma unroll
            for (int hrow = 0; hrow < 2; ++hrow) {
                int r = row + hrow * 8;
                size_t i0 = (size_t)r * N + col;
                Cout[i0]     = c[mi][nt][hrow * 2 + 0];
                Cout[i0 + 1] = c[mi][nt][hrow * 2 + 1];
            }
        }
}

// ---------------- product-key routing: top8 x top8 -> top8, softmax ----------------
__global__ void __launch_bounds__(256)
routing_kernel(const float* __restrict__ Q, const float* __restrict__ keys,
               int* __restrict__ eidx, float* __restrict__ probs)
{
    const int warp = threadIdx.x >> 5, lane = threadIdx.x & 31;
    const int m = blockIdx.x * 8 + warp;

    __shared__ float s_q[8][128];
    __shared__ float s_tsx[8][8], s_tsy[8][8];
    __shared__ int   s_tix[8][8], s_tiy[8][8];
    __shared__ float s_sel[8][8];
    __shared__ int   s_pos[8][8];

    const int j0 = (m >> 1);
    const int j1 = 4096 + (m >> 1);
    const int o  = (m & 1) * 64;
    s_q[warp][lane]           = Q[j0 * RET + o + lane];
    s_q[warp][lane + 32]      = Q[j0 * RET + o + lane + 32];
    s_q[warp][64 + lane]      = Q[j1 * RET + o + lane];
    s_q[warp][64 + lane + 32] = Q[j1 * RET + o + lane + 32];
    __syncwarp();

    float rx0 = 0.f, rx1 = 0.f, ry0 = 0.f, ry1 = 0.f;
#pragma unroll 8
    for (int d = 0; d < 64; ++d) {
        float qx = s_q[warp][d], qy = s_q[warp][64 + d];
        rx0 += qx * keys[d * 64 + lane];
        rx1 += qx * keys[d * 64 + lane + 32];
        ry0 += qy * keys[4096 + d * 64 + lane];
        ry1 += qy * keys[4096 + d * 64 + lane + 32];
    }

#pragma unroll 1
    for (int r = 0; r < 8; ++r) {
        float v; int i;
        if (rx0 >= rx1) { v = rx0; i = lane; } else { v = rx1; i = lane + 32; }
#pragma unroll
        for (int s = 16; s; s >>= 1) {
            float ov = __shfl_xor_sync(0xffffffffu, v, s);
            int   oi = __shfl_xor_sync(0xffffffffu, i, s);
            if (ov > v || (ov == v && oi < i)) { v = ov; i = oi; }
        }
        if (lane == 0) { s_tsx[warp][r] = v; s_tix[warp][r] = i; }
        if (i == lane)      rx0 = -INFINITY;
        if (i == lane + 32) rx1 = -INFINITY;
    }
#pragma unroll 1
    for (int r = 0; r < 8; ++r) {
        float v; int i;
        if (ry0 >= ry1) { v = ry0; i = lane; } else { v = ry1; i = lane + 32; }
#pragma unroll
        for (int s = 16; s; s >>= 1) {
            float ov = __shfl_xor_sync(0xffffffffu, v, s);
            int   oi = __shfl_xor_sync(0xffffffffu, i, s);
            if (ov > v || (ov == v && oi < i)) { v = ov; i = oi; }
        }
        if (lane == 0) { s_tsy[warp][r] = v; s_tiy[warp][r] = i; }
        if (i == lane)      ry0 = -INFINITY;
        if (i == lane + 32) ry1 = -INFINITY;
    }
    __syncwarp();

    float c0 = s_tsx[warp][lane >> 3]        + s_tsy[warp][lane & 7];
    float c1 = s_tsx[warp][(lane + 32) >> 3] + s_tsy[warp][(lane + 32) & 7];
#pragma unroll 1
    for (int r = 0; r < 8; ++r) {
        float v; int p;
        if (c0 >= c1) { v = c0; p = lane; } else { v = c1; p = lane + 32; }
#pragma unroll
        for (int s = 16; s; s >>= 1) {
            float ov = __shfl_xor_sync(0xffffffffu, v, s);
            int   op = __shfl_xor_sync(0xffffffffu, p, s);
            if (ov > v || (ov == v && op < p)) { v = ov; p = op; }
        }
        if (lane == 0) { s_sel[warp][r] = v; s_pos[warp][r] = p; }
        if (p == lane)      c0 = -INFINITY;
        if (p == lane + 32) c1 = -INFINITY;
    }
    __syncwarp();

    if (lane < 8) {
        float mx = s_sel[warp][0];
        float e  = expf(s_sel[warp][lane] - mx);
        float sum = e;
#pragma unroll
        for (int s = 4; s; s >>= 1) sum += __shfl_xor_sync(0xffu, sum, s);
        int p  = s_pos[warp][lane];
        int ex = s_tix[warp][p >> 3] * 64 + s_tiy[warp][p & 7];
        eidx[m * TOPK + lane]  = ex;
        probs[m * TOPK + lane] = e / sum;
    }
}

// ---------------- per-token expert compute (writes g_es, no out RMW) ----------------
__global__ void __launch_bounds__(256)
expert_kernel(const float* __restrict__ x, const float* __restrict__ down_embed,
              const float* __restrict__ up_embed, const int* __restrict__ eidx,
              const float* __restrict__ probs, float* __restrict__ es)
{
    const int n = blockIdx.x;
    __shared__ __align__(16) float sx[HID];
    __shared__ float coeff[TOPK];
    __shared__ int   se[TOPK];

    const int tid = threadIdx.x;
    const float4* xin = (const float4*)(x + (size_t)n * HID);
    float4* sx4 = (float4*)sx;
    sx4[tid]       = xin[tid];
    sx4[tid + 256] = xin[tid + 256];
    if (tid < TOPK) se[tid] = eidx[n * TOPK + tid];
    __syncthreads();

    const int w = tid >> 5, lane = tid & 31;
    {
        const float* de = down_embed + (size_t)se[w] * HID;
        float acc = 0.f;
#pragma unroll
        for (int i = 0; i < 64; ++i) acc += sx[i * 32 + lane] * de[i * 32 + lane];
#pragma unroll
        for (int s = 16; s; s >>= 1) acc += __shfl_xor_sync(0xffffffffu, acc, s);
        if (lane == 0)
            coeff[w] = acc / (1.f + expf(-acc)) * probs[n * TOPK + w];
    }
    __syncthreads();

    float cc[TOPK]; const float4* ue4[TOPK];
#pragma unroll
    for (int k = 0; k < TOPK; ++k) {
        cc[k]  = coeff[k];
        ue4[k] = (const float4*)(up_embed + (size_t)se[k] * HID);
    }

    float4* es4 = (float4*)(es + (size_t)n * HID);
#pragma unroll
    for (int h = tid; h < HID / 4; h += 256) {
        float4 acc = make_float4(0.f, 0.f, 0.f, 0.f);
#pragma unroll
        for (int k = 0; k < TOPK; ++k) {
            float4 u = ue4[k][h];
            acc.x += cc[k] * u.x; acc.y += cc[k] * u.y;
            acc.z += cc[k] * u.z; acc.w += cc[k] * u.w;
        }
        es4[h] = acc;
    }
}

// ---------------- launch ----------------
extern "C" void kernel_launch(void* const* d_in, const int* in_sizes, int n_in,
                              void* d_out, int out_size) {
    (void)in_sizes; (void)n_in; (void)out_size;
    const float* x    = (const float*)d_in[0];
    const float* Wq   = (const float*)d_in[1];
    const float* keys = (const float*)d_in[2];
    const float* de   = (const float*)d_in[3];
    const float* ue   = (const float*)d_in[4];
    const float* gw   = (const float*)d_in[5];
    const float* uw   = (const float*)d_in[6];
    const float* dw   = (const float*)d_in[7];
    float* out = (float*)d_out;

    void *x16, *gw16, *uw16, *dw16, *G16, *h16, *esp;
    void *xh, *xl, *wqh, *wql, *Qp, *idxp, *pp;
    cudaGetSymbolAddress(&x16,  g_x16);   cudaGetSymbolAddress(&gw16, g_gw16);
    cudaGetSymbolAddress(&uw16, g_uw16);  cudaGetSymbolAddress(&dw16, g_dw16);
    cudaGetSymbolAddress(&G16,  g_G16);   cudaGetSymbolAddress(&h16,  g_h16);
    cudaGetSymbolAddress(&esp,  g_es);
    cudaGetSymbolAddress(&xh,   g_x_hi);  cudaGetSymbolAddress(&xl,   g_x_lo);
    cudaGetSymbolAddress(&wqh,  g_wq_hi); cudaGetSymbolAddress(&wql,  g_wq_lo);
    cudaGetSymbolAddress(&Qp,   g_Q);
    cudaGetSymbolAddress(&idxp, g_eidx);  cudaGetSymbolAddress(&pp,   g_prob);

    const int SMEM_H  = 3 * 29184;   // 87552
    const int SMEM_3X = 3 * 58368;   // 175104
    cudaFuncSetAttribute(gemmh_kernel,  cudaFuncAttributeMaxDynamicSharedMemorySize, SMEM_H);
    cudaFuncSetAttribute(gemm3x_kernel, cudaFuncAttributeMaxDynamicSharedMemorySize, SMEM_3X);

    // side stream + fork/join events: created once, on the (uncaptured)
    // correctness call; reused identically on the capture call.
    static cudaStream_t s_side = nullptr;
    static cudaEvent_t  ev_fork = nullptr, ev_join = nullptr;
    if (s_side == nullptr) {
        cudaStreamCreateWithFlags(&s_side, cudaStreamNonBlocking);
        cudaEventCreateWithFlags(&ev_fork, cudaEventDisableTiming);
        cudaEventCreateWithFlags(&ev_join, cudaEventDisableTiming);
    }

    // ---- prep (main stream) ----
    xprep_kernel<<<2048, 256>>>(x, (__half*)x16, (bf16*)xh, (bf16*)xl, NTOK * HID);
    wcvt_kernel<<<4096, 256>>>(gw, (__half*)gw16, uw, (__half*)uw16, dw, (__half*)dw16, HID * INTER);
    splitwq_kernel<<<256, 256>>>(Wq, (bf16*)wqh, (bf16*)wql, HID * RET);

    // ---- fork: side stream runs the routing/expert branch ----
    cudaEventRecord(ev_fork, 0);
    cudaStreamWaitEvent(s_side, ev_fork, 0);

    gemm3x_kernel<<<dim3(1, NTOK / 256), 256, SMEM_3X, s_side>>>(
        (const bf16*)xh, (const bf16*)xl, (const bf16*)wqh, (const bf16*)wql,
        NTOK, RET, HID, (float*)Qp);
    routing_kernel<<<NTOK / 8, 256, 0, s_side>>>((const float*)Qp, keys, (int*)idxp, (float*)pp);
    expert_kernel<<<NTOK, 256, 0, s_side>>>(x, de, ue, (const int*)idxp, (const float*)pp, (float*)esp);
    cudaEventRecord(ev_join, s_side);

    // ---- main stream: gate -> up (overlapped with side branch) ----
    gemmh_kernel<<<dim3(INTER / 128, NTOK / 256), 256, SMEM_H>>>(
        (const __half*)x16, (const __half*)gw16, NTOK, INTER, HID,
        nullptr, nullptr, (__half*)G16, nullptr, 2);
    gemmh_kernel<<<dim3(INTER / 128, NTOK / 256), 256, SMEM_H>>>(
        (const __half*)x16, (const __half*)uw16, NTOK, INTER, HID,
        nullptr, (const __half*)G16, (__half*)h16, nullptr, 1);

    // ---- join, then down GEMM with fused expert add ----
    cudaStreamWaitEvent(0, ev_join, 0);
    gemmh_kernel<<<dim3(HID / 128, NTOK / 256), 256, SMEM_H>>>(
        (const __half*)h16, (const __half*)dw16, NTOK, HID, INTER,
        out, nullptr, nullptr, (const float*)esp, 3);
}